// round 9
// baseline (speedup 1.0000x reference)
#include <cuda_runtime.h>
#include <cuda_fp16.h>
#include <cstdint>
#include <math.h>

#define BB 4
#define SSEQ 2048
#define DIMX 512
#define HEADS 8
#define DHEAD 64
#define INNER 512
#define NROWS (BB * SSEQ)   // 8192

// ---------------- device scratch -------------------------------------------
__device__ __half g_xh[NROWS * DIMX],      g_xl[NROWS * DIMX];
__device__ __half g_wqh[3 * INNER * DIMX], g_wql[3 * INNER * DIMX];
__device__ __half g_woh[DIMX * INNER];
__device__ __half g_q[NROWS * INNER];   // [bh][s][64]
__device__ __half g_k[NROWS * INNER];
__device__ __half g_v[NROWS * INNER];
__device__ __half g_a[NROWS * INNER];   // [b*s][512]

// ---------------- helpers ---------------------------------------------------
__device__ __forceinline__ uint32_t smem_u32(const void* p) {
    uint32_t a;
    asm("{ .reg .u64 t; cvta.to.shared.u64 t, %1; cvt.u32.u64 %0, t; }" : "=r"(a) : "l"(p));
    return a;
}
__device__ __forceinline__ void ldsm4(uint32_t& r0, uint32_t& r1, uint32_t& r2,
                                      uint32_t& r3, uint32_t addr) {
    asm volatile("ldmatrix.sync.aligned.m8n8.x4.shared.b16 {%0,%1,%2,%3}, [%4];"
                 : "=r"(r0), "=r"(r1), "=r"(r2), "=r"(r3) : "r"(addr));
}
__device__ __forceinline__ void ldsm4t(uint32_t& r0, uint32_t& r1, uint32_t& r2,
                                       uint32_t& r3, uint32_t addr) {
    asm volatile("ldmatrix.sync.aligned.m8n8.x4.trans.shared.b16 {%0,%1,%2,%3}, [%4];"
                 : "=r"(r0), "=r"(r1), "=r"(r2), "=r"(r3) : "r"(addr));
}
__device__ __forceinline__ void mma_f16(float* c, const uint32_t a[4],
                                        uint32_t b0, uint32_t b1) {
    asm volatile(
        "mma.sync.aligned.m16n8k16.row.col.f32.f16.f16.f32 "
        "{%0,%1,%2,%3}, {%4,%5,%6,%7}, {%8,%9}, {%0,%1,%2,%3};"
        : "+f"(c[0]), "+f"(c[1]), "+f"(c[2]), "+f"(c[3])
        : "r"(a[0]), "r"(a[1]), "r"(a[2]), "r"(a[3]), "r"(b0), "r"(b1));
}
__device__ __forceinline__ void cp16(uint32_t dst, const void* src) {
    asm volatile("cp.async.cg.shared.global [%0], [%1], 16;" :: "r"(dst), "l"(src));
}
#define CP_COMMIT() asm volatile("cp.async.commit_group;" ::: "memory")
#define CP_WAIT1()  asm volatile("cp.async.wait_group 1;" ::: "memory")

__device__ __forceinline__ uint32_t pkh(float a, float b) {   // a in low half
    __half2 x = __floats2half2_rn(a, b);
    return *reinterpret_cast<uint32_t*>(&x);
}
// 16B-chunk swizzle within 128B rows (conflict-free ldmatrix)
__device__ __forceinline__ uint32_t swz(int r, int c) {
    return (uint32_t)r * 128u + (uint32_t)((c ^ (r & 7)) & 7) * 16u;
}

// ---------------- convert kernels (fp16 hi/lo, unscaled) ---------------------
__global__ void k_split_h(const float* __restrict__ in, __half* __restrict__ hi,
                          __half* __restrict__ lo, int n) {
    int i = blockIdx.x * blockDim.x + threadIdx.x;
    if (i < n) {
        float f = in[i];
        __half h = __float2half_rn(f);
        hi[i] = h;
        lo[i] = __float2half_rn(f - __half2float(h));
    }
}
template <bool LO>
__global__ void k_splitT_h(const float* __restrict__ in, __half* __restrict__ hi,
                           __half* __restrict__ lo, int K, int N) {
    int i = blockIdx.x * blockDim.x + threadIdx.x;
    if (i < K * N) {
        int n = i / K, k = i % K;
        float f = in[(size_t)k * N + n];
        __half h = __float2half_rn(f);
        hi[i] = h;
        if (LO) lo[i] = __float2half_rn(f - __half2float(h));
    }
}

// ---------------- fp16x3 GEMM, 256 threads, 2 CTAs/SM ------------------------
// tile 128x128, warp grid 4x2, warp tile 32x64, k-chunk 32.
// Stage layout (32KB): A rows 128x128B (chunks 0-3 hi | 4-7 lo), B at +16K.
// MODE 0: q/k tiles (n0<1024) 3 terms; V tiles 1 term. -> q/k/v fp16 [bh][s][d]
// MODE 1: 1 term, fp32 + bias.
template <int MODE>
__global__ void __launch_bounds__(256, 2)
gemm_mma(const __half* __restrict__ Ah, const __half* __restrict__ Al,
         const __half* __restrict__ Bh, const __half* __restrict__ Bl,
         int Kd,
         __half* __restrict__ q, __half* __restrict__ k, __half* __restrict__ v,
         const float* __restrict__ bias, float* __restrict__ outp) {
    extern __shared__ char smc[];
    const uint32_t sb = smem_u32(smc);
    const int tid = threadIdx.x, w = tid >> 5, lane = tid & 31;
    const int m0 = blockIdx.y * 128, n0 = blockIdx.x * 128;
    const int wm = w & 3, wn = w >> 2;
    const uint32_t STG = 32768;
    const bool full = (MODE == 0 && n0 < 1024);

    float acc[2][8][4] = {};

    auto issue = [&](int kc, int stg) {
        uint32_t base = sb + (uint32_t)stg * STG;
#pragma unroll
        for (int i = tid; i < 1024; i += 256) {
            int r = i >> 3, c = i & 7;
            uint32_t off = swz(r, c);
            int kk = kc + (c & 3) * 8;
            if (c < 4) {
                cp16(base + off,         Ah + (size_t)(m0 + r) * Kd + kk);
                cp16(base + 16384 + off, Bh + (size_t)(n0 + r) * Kd + kk);
            } else if (full) {
                cp16(base + off,         Al + (size_t)(m0 + r) * Kd + kk);
                cp16(base + 16384 + off, Bl + (size_t)(n0 + r) * Kd + kk);
            }
        }
    };

    const int nch = Kd / 32;   // 16
    issue(0, 0); CP_COMMIT();

    for (int kc = 0; kc < nch; kc++) {
        if (kc + 1 < nch) issue((kc + 1) * 32, (kc + 1) & 1);
        CP_COMMIT();
        CP_WAIT1();
        __syncthreads();

        const uint32_t As = sb + (uint32_t)(kc & 1) * STG;
        const uint32_t Bs = As + 16384;
#pragma unroll
        for (int ks = 0; ks < 2; ks++) {
            uint32_t ah[2][4], al[2][4];
#pragma unroll
            for (int mt = 0; mt < 2; mt++) {
                int rr = 32 * wm + 16 * mt + (lane & 7) + ((lane >> 3) & 1) * 8;
                int cc = 2 * ks + (lane >> 4);
                ldsm4(ah[mt][0], ah[mt][1], ah[mt][2], ah[mt][3], As + swz(rr, cc));
                if (full)
                    ldsm4(al[mt][0], al[mt][1], al[mt][2], al[mt][3],
                          As + swz(rr, cc + 4));
            }
#pragma unroll
            for (int nb = 0; nb < 4; nb++) {
                int rr = 64 * wn + 16 * nb + (lane & 7) + ((lane >> 4) ? 8 : 0);
                int cc = 2 * ks + ((lane >> 3) & 1);
                uint32_t bh0, bh1, bh2, bh3;
                ldsm4(bh0, bh1, bh2, bh3, Bs + swz(rr, cc));
#pragma unroll
                for (int mt = 0; mt < 2; mt++) {
                    mma_f16(acc[mt][2 * nb],     ah[mt], bh0, bh1);
                    mma_f16(acc[mt][2 * nb + 1], ah[mt], bh2, bh3);
                }
                if (full) {
                    uint32_t bl0, bl1, bl2, bl3;
                    ldsm4(bl0, bl1, bl2, bl3, Bs + swz(rr, cc + 4));
#pragma unroll
                    for (int mt = 0; mt < 2; mt++) {
                        mma_f16(acc[mt][2 * nb],     ah[mt], bl0, bl1);
                        mma_f16(acc[mt][2 * nb + 1], ah[mt], bl2, bl3);
                        mma_f16(acc[mt][2 * nb],     al[mt], bh0, bh1);
                        mma_f16(acc[mt][2 * nb + 1], al[mt], bh2, bh3);
                    }
                }
            }
        }
        __syncthreads();
    }

    // epilogue
#pragma unroll
    for (int mt = 0; mt < 2; mt++) {
#pragma unroll
        for (int i = 0; i < 2; i++) {
            const int gm = m0 + 32 * wm + 16 * mt + (lane >> 2) + i * 8;
#pragma unroll
            for (int nt = 0; nt < 8; nt++) {
                const int gn = n0 + 64 * wn + 8 * nt + 2 * (lane & 3);
                float v0 = acc[mt][nt][2 * i], v1 = acc[mt][nt][2 * i + 1];
                if (MODE == 0) {
                    const int seg = gn >> 9, nn = gn & 511;
                    const int h = nn >> 6, d = nn & 63;
                    const int bI = gm >> 11, s = gm & 2047;
                    size_t idx = ((size_t)((bI * 8 + h) * 2048 + s)) * 64 + d;
                    __half* dst = (seg == 0) ? q : (seg == 1) ? k : v;
                    *reinterpret_cast<uint32_t*>(dst + idx) = pkh(v0, v1);
                } else {
                    float2 o = make_float2(v0 + bias[gn], v1 + bias[gn + 1]);
                    *reinterpret_cast<float2*>(outp + (size_t)gm * 512 + gn) = o;
                }
            }
        }
    }
}

// ---------------- attention: fp16 HMMA flash, 2 stages, 2 CTAs/SM ------------
__global__ void __launch_bounds__(256, 2)
attn_mma(const __half* __restrict__ qg, const __half* __restrict__ kg,
         const __half* __restrict__ vg, const float* __restrict__ log_temp,
         __half* __restrict__ aout) {
    extern __shared__ char smc[];
    const uint32_t sb = smem_u32(smc);
    const int tid = threadIdx.x, w = tid >> 5, lane = tid & 31;
    const int q0 = blockIdx.x * 128;
    const int bh = blockIdx.y, b = bh >> 3, h = bh & 7;
    const uint32_t KO = 0, VO = 16384, STG = 32768, QO = 65536;

    const float scale = __expf(*log_temp);
    const size_t bho = (size_t)bh * 2048 * 64;

    // Q -> smem
#pragma unroll
    for (int i = tid; i < 1024; i += 256) {
        int r = i >> 3, c = i & 7;
        *reinterpret_cast<uint4*>(smc + QO + swz(r, c)) =
            *reinterpret_cast<const uint4*>(qg + bho + (size_t)(q0 + r) * 64 + c * 8);
    }

    auto issue = [&](int t, int stg) {
        const size_t o = bho + (size_t)t * 128 * 64;
        uint32_t base = sb + (uint32_t)stg * STG;
#pragma unroll
        for (int i = tid; i < 1024; i += 256) {
            int r = i >> 3, c = i & 7;
            uint32_t off = swz(r, c);
            size_t g = o + (size_t)r * 64 + c * 8;
            cp16(base + KO + off, kg + g);
            cp16(base + VO + off, vg + g);
        }
    };
    issue(0, 0); CP_COMMIT();
    __syncthreads();   // Q visible

    uint32_t aq[4][4];
    {
        int rr = 16 * w + (lane & 7) + ((lane >> 3) & 1) * 8;
#pragma unroll
        for (int ks = 0; ks < 4; ks++) {
            int cc = 2 * ks + (lane >> 4);
            ldsm4(aq[ks][0], aq[ks][1], aq[ks][2], aq[ks][3], sb + QO + swz(rr, cc));
        }
    }

    float O[8][4] = {};
    float l0 = 0.f, l1 = 0.f;
    const int rg = 16 * w + (lane >> 2);
    const int qi0 = q0 + rg, qi1 = qi0 + 8;

    for (int t = 0; t < 16; t++) {
        if (t + 1 < 16) issue(t + 1, (t + 1) & 1);
        CP_COMMIT();
        CP_WAIT1();
        __syncthreads();

        const uint32_t stgb = sb + (uint32_t)(t & 1) * STG;
        const uint32_t Ks = stgb + KO, Vs = stgb + VO;

        uint32_t ep[16][2];
        // S = Q @ K^T in two 64-col halves (register pressure cap)
#pragma unroll
        for (int half = 0; half < 2; half++) {
            float S[8][4] = {};
#pragma unroll
            for (int ks = 0; ks < 4; ks++) {
#pragma unroll
                for (int ntp = 0; ntp < 4; ntp++) {
                    uint32_t b0, b1, b2, b3;
                    int rr = 16 * (4 * half + ntp) + (lane & 7) + ((lane >> 4) ? 8 : 0);
                    int cc = 2 * ks + ((lane >> 3) & 1);
                    ldsm4(b0, b1, b2, b3, Ks + swz(rr, cc));
                    mma_f16(S[2 * ntp],     aq[ks], b0, b1);
                    mma_f16(S[2 * ntp + 1], aq[ks], b2, b3);
                }
            }
            // exp + diag mask, pack P to fp16
#pragma unroll
            for (int s = 0; s < 8; s++) {
                int nt = 8 * half + s;
                int jc = t * 128 + 8 * nt + 2 * (lane & 3);
                float e0 = (jc     == qi0) ? 0.f : __expf(S[s][0] * scale);
                float e1 = (jc + 1 == qi0) ? 0.f : __expf(S[s][1] * scale);
                float e2 = (jc     == qi1) ? 0.f : __expf(S[s][2] * scale);
                float e3 = (jc + 1 == qi1) ? 0.f : __expf(S[s][3] * scale);
                l0 += e0 + e1;
                l1 += e2 + e3;
                ep[nt][0] = pkh(e0, e1);
                ep[nt][1] = pkh(e2, e3);
            }
        }

        // O += P @ V
#pragma unroll
        for (int ks = 0; ks < 8; ks++) {
            uint32_t ap[4] = { ep[2 * ks][0], ep[2 * ks][1],
                               ep[2 * ks + 1][0], ep[2 * ks + 1][1] };
#pragma unroll
            for (int ntp = 0; ntp < 4; ntp++) {
                uint32_t b0, b1, b2, b3;
                int rr = 16 * ks + (lane & 7) + ((lane >> 3) & 1) * 8;
                int cc = 2 * ntp + (lane >> 4);
                ldsm4t(b0, b1, b2, b3, Vs + swz(rr, cc));
                mma_f16(O[2 * ntp],     ap, b0, b1);
                mma_f16(O[2 * ntp + 1], ap, b2, b3);
            }
        }
        __syncthreads();
    }

    l0 += __shfl_xor_sync(0xffffffffu, l0, 1);
    l0 += __shfl_xor_sync(0xffffffffu, l0, 2);
    l1 += __shfl_xor_sync(0xffffffffu, l1, 1);
    l1 += __shfl_xor_sync(0xffffffffu, l1, 2);
    const float inv0 = 1.f / l0, inv1 = 1.f / l1;

#pragma unroll
    for (int i = 0; i < 2; i++) {
        const float inv = i ? inv1 : inv0;
        const size_t gm = (size_t)(b * 2048 + q0 + rg + i * 8);
#pragma unroll
        for (int nt = 0; nt < 8; nt++) {
            const int d = 8 * nt + 2 * (lane & 3);
            size_t idx = gm * INNER + h * DHEAD + d;
            *reinterpret_cast<uint32_t*>(aout + idx) =
                pkh(O[nt][2 * i] * inv, O[nt][2 * i + 1] * inv);
        }
    }
}

// ---------------- launch -----------------------------------------------------
extern "C" void kernel_launch(void* const* d_in, const int* in_sizes, int n_in,
                              void* d_out, int out_size) {
    const float* x        = (const float*)d_in[0];
    const float* W_qkv    = (const float*)d_in[1];
    const float* log_temp = (const float*)d_in[2];
    const float* W_out    = (const float*)d_in[3];
    const float* b_out    = (const float*)d_in[4];
    float* out = (float*)d_out;

    __half *xh, *xl, *wqh, *wql, *woh, *q, *k, *v, *a;
    cudaGetSymbolAddress((void**)&xh, g_xh);   cudaGetSymbolAddress((void**)&xl, g_xl);
    cudaGetSymbolAddress((void**)&wqh, g_wqh); cudaGetSymbolAddress((void**)&wql, g_wql);
    cudaGetSymbolAddress((void**)&woh, g_woh);
    cudaGetSymbolAddress((void**)&q, g_q);
    cudaGetSymbolAddress((void**)&k, g_k);
    cudaGetSymbolAddress((void**)&v, g_v);
    cudaGetSymbolAddress((void**)&a, g_a);

    const int GSM = 65536;   // 2 stages x 32KB
    const int ASM = 81920;   // 2 stages x 32KB + Q 16KB
    cudaFuncSetAttribute(gemm_mma<0>, cudaFuncAttributeMaxDynamicSharedMemorySize, GSM);
    cudaFuncSetAttribute(gemm_mma<1>, cudaFuncAttributeMaxDynamicSharedMemorySize, GSM);
    cudaFuncSetAttribute(attn_mma,    cudaFuncAttributeMaxDynamicSharedMemorySize, ASM);

    k_split_h<<<(NROWS * DIMX + 255) / 256, 256>>>(x, xh, xl, NROWS * DIMX);
    k_splitT_h<true><<<(DIMX * 3 * INNER + 255) / 256, 256>>>(W_qkv, wqh, wql,
                                                              DIMX, 3 * INNER);
    k_splitT_h<false><<<(INNER * DIMX + 255) / 256, 256>>>(W_out, woh, nullptr,
                                                           INNER, DIMX);

    // 1) QKV projection: q/k tiles 3-term fp16x3, V tiles 1-term
    gemm_mma<0><<<dim3(12, 64), 256, GSM>>>(xh, xl, wqh, wql, DIMX,
                                            q, k, v, nullptr, nullptr);
    // 2) attention (fp32-acc everywhere)
    attn_mma<<<dim3(SSEQ / 128, BB * HEADS), 256, ASM>>>(q, k, v, log_temp, a);
    // 3) output projection, 1-term + bias -> fp32
    gemm_mma<1><<<dim3(4, 64), 256, GSM>>>(a, a, woh, woh, INNER,
                                           nullptr, nullptr, nullptr, b_out, out);
}

// round 10
// speedup vs baseline: 1.2329x; 1.2329x over previous
#include <cuda_runtime.h>
#include <cuda_fp16.h>
#include <cstdint>
#include <math.h>

#define BB 4
#define SSEQ 2048
#define DIMX 512
#define HEADS 8
#define DHEAD 64
#define INNER 512
#define NROWS (BB * SSEQ)   // 8192

// ---------------- device scratch -------------------------------------------
__device__ __half g_x[NROWS * DIMX];
__device__ __half g_wq[3 * INNER * DIMX];   // W_qkv^T
__device__ __half g_wo[DIMX * INNER];       // W_out^T
__device__ __half g_q[NROWS * INNER];       // [bh][s][64]
__device__ __half g_k[NROWS * INNER];
__device__ __half g_v[NROWS * INNER];
__device__ __half g_a[NROWS * INNER];       // [b*s][512]

// ---------------- helpers ---------------------------------------------------
__device__ __forceinline__ uint32_t smem_u32(const void* p) {
    uint32_t a;
    asm("{ .reg .u64 t; cvta.to.shared.u64 t, %1; cvt.u32.u64 %0, t; }" : "=r"(a) : "l"(p));
    return a;
}
__device__ __forceinline__ void ldsm4(uint32_t& r0, uint32_t& r1, uint32_t& r2,
                                      uint32_t& r3, uint32_t addr) {
    asm volatile("ldmatrix.sync.aligned.m8n8.x4.shared.b16 {%0,%1,%2,%3}, [%4];"
                 : "=r"(r0), "=r"(r1), "=r"(r2), "=r"(r3) : "r"(addr));
}
__device__ __forceinline__ void ldsm4t(uint32_t& r0, uint32_t& r1, uint32_t& r2,
                                       uint32_t& r3, uint32_t addr) {
    asm volatile("ldmatrix.sync.aligned.m8n8.x4.trans.shared.b16 {%0,%1,%2,%3}, [%4];"
                 : "=r"(r0), "=r"(r1), "=r"(r2), "=r"(r3) : "r"(addr));
}
__device__ __forceinline__ void mma_f16(float* c, const uint32_t a[4],
                                        uint32_t b0, uint32_t b1) {
    asm volatile(
        "mma.sync.aligned.m16n8k16.row.col.f32.f16.f16.f32 "
        "{%0,%1,%2,%3}, {%4,%5,%6,%7}, {%8,%9}, {%0,%1,%2,%3};"
        : "+f"(c[0]), "+f"(c[1]), "+f"(c[2]), "+f"(c[3])
        : "r"(a[0]), "r"(a[1]), "r"(a[2]), "r"(a[3]), "r"(b0), "r"(b1));
}
__device__ __forceinline__ void cp16(uint32_t dst, const void* src) {
    asm volatile("cp.async.cg.shared.global [%0], [%1], 16;" :: "r"(dst), "l"(src));
}
#define CP_COMMIT() asm volatile("cp.async.commit_group;" ::: "memory")
#define CP_WAIT1()  asm volatile("cp.async.wait_group 1;" ::: "memory")

__device__ __forceinline__ uint32_t pkh(float a, float b) {   // a in low half
    __half2 x = __floats2half2_rn(a, b);
    return *reinterpret_cast<uint32_t*>(&x);
}
// 16B-chunk swizzle within 128B rows (conflict-free ldmatrix)
__device__ __forceinline__ uint32_t swz(int r, int c) {
    return (uint32_t)r * 128u + (uint32_t)((c ^ (r & 7)) & 7) * 16u;
}

// ---------------- convert kernels (plain fp16 cast) --------------------------
__global__ void k_cast(const float* __restrict__ in, __half* __restrict__ o, int n) {
    int i = blockIdx.x * blockDim.x + threadIdx.x;
    if (i < n) o[i] = __float2half_rn(in[i]);
}
__global__ void k_castT(const float* __restrict__ in, __half* __restrict__ o,
                        int K, int N) {
    int i = blockIdx.x * blockDim.x + threadIdx.x;
    if (i < K * N) {
        int n = i / K, k = i % K;
        o[i] = __float2half_rn(in[(size_t)k * N + n]);
    }
}

// ---------------- fp16 1-term GEMM, 512 threads (R8 shape) -------------------
// tile 128x128, warp grid 4x4, warp tile 32x32, k-chunk 64, 2x32KB stages.
// MODE 0: -> q/k/v fp16 per-head layout [bh][s][d];  MODE 1: fp32 + bias.
template <int MODE>
__global__ void __launch_bounds__(512, 1)
gemm_mma(const __half* __restrict__ Ah, const __half* __restrict__ Bh, int Kd,
         __half* __restrict__ q, __half* __restrict__ k, __half* __restrict__ v,
         const float* __restrict__ bias, float* __restrict__ outp) {
    extern __shared__ char smc[];
    const uint32_t sb = smem_u32(smc);
    const int tid = threadIdx.x, w = tid >> 5, lane = tid & 31;
    const int m0 = blockIdx.y * 128, n0 = blockIdx.x * 128;
    const int wm = w & 3, wn = w >> 2;
    const uint32_t STG = 32768;   // A 16K | B 16K

    float acc[2][4][4] = {};

    auto issue = [&](int kc, int stg) {
        uint32_t base = sb + (uint32_t)stg * STG;
#pragma unroll
        for (int i = tid; i < 1024; i += 512) {
            int r = i >> 3, c = i & 7;
            uint32_t off = swz(r, c);
            cp16(base + off,         Ah + (size_t)(m0 + r) * Kd + kc + c * 8);
            cp16(base + 16384 + off, Bh + (size_t)(n0 + r) * Kd + kc + c * 8);
        }
    };

    const int nch = Kd / 64;
    issue(0, 0); CP_COMMIT();

    for (int kc = 0; kc < nch; kc++) {
        if (kc + 1 < nch) issue((kc + 1) * 64, (kc + 1) & 1);
        CP_COMMIT();
        CP_WAIT1();
        __syncthreads();

        const uint32_t As = sb + (uint32_t)(kc & 1) * STG;
        const uint32_t Bs = As + 16384;
#pragma unroll
        for (int ks = 0; ks < 4; ks++) {
            uint32_t ah[2][4];
#pragma unroll
            for (int mt = 0; mt < 2; mt++) {
                int rr = 32 * wm + 16 * mt + (lane & 7) + ((lane >> 3) & 1) * 8;
                int cc = 2 * ks + (lane >> 4);
                ldsm4(ah[mt][0], ah[mt][1], ah[mt][2], ah[mt][3], As + swz(rr, cc));
            }
#pragma unroll
            for (int ntp = 0; ntp < 2; ntp++) {
                int rr = 32 * wn + 16 * ntp + (lane & 7) + ((lane >> 4) ? 8 : 0);
                int cc = 2 * ks + ((lane >> 3) & 1);
                uint32_t b0, b1, b2, b3;
                ldsm4(b0, b1, b2, b3, Bs + swz(rr, cc));
#pragma unroll
                for (int mt = 0; mt < 2; mt++) {
                    mma_f16(acc[mt][2 * ntp],     ah[mt], b0, b1);
                    mma_f16(acc[mt][2 * ntp + 1], ah[mt], b2, b3);
                }
            }
        }
        __syncthreads();
    }

    // epilogue
#pragma unroll
    for (int mt = 0; mt < 2; mt++) {
#pragma unroll
        for (int i = 0; i < 2; i++) {
            const int gm = m0 + 32 * wm + 16 * mt + (lane >> 2) + i * 8;
#pragma unroll
            for (int nt = 0; nt < 4; nt++) {
                const int gn = n0 + 32 * wn + 8 * nt + 2 * (lane & 3);
                float v0 = acc[mt][nt][2 * i], v1 = acc[mt][nt][2 * i + 1];
                if (MODE == 0) {
                    const int seg = gn >> 9, nn = gn & 511;
                    const int h = nn >> 6, d = nn & 63;
                    const int bI = gm >> 11, s = gm & 2047;
                    size_t idx = ((size_t)((bI * 8 + h) * 2048 + s)) * 64 + d;
                    __half* dst = (seg == 0) ? q : (seg == 1) ? k : v;
                    *reinterpret_cast<uint32_t*>(dst + idx) = pkh(v0, v1);
                } else {
                    float2 o = make_float2(v0 + bias[gn], v1 + bias[gn + 1]);
                    *reinterpret_cast<float2*>(outp + (size_t)gm * 512 + gn) = o;
                }
            }
        }
    }
}

// ---------------- attention: fp16 HMMA flash (R9 config) ---------------------
__global__ void __launch_bounds__(256, 2)
attn_mma(const __half* __restrict__ qg, const __half* __restrict__ kg,
         const __half* __restrict__ vg, const float* __restrict__ log_temp,
         __half* __restrict__ aout) {
    extern __shared__ char smc[];
    const uint32_t sb = smem_u32(smc);
    const int tid = threadIdx.x, w = tid >> 5, lane = tid & 31;
    const int q0 = blockIdx.x * 128;
    const int bh = blockIdx.y, b = bh >> 3, h = bh & 7;
    const uint32_t KO = 0, VO = 16384, STG = 32768, QO = 65536;

    const float scale = __expf(*log_temp);
    const size_t bho = (size_t)bh * 2048 * 64;

    // Q -> smem
#pragma unroll
    for (int i = tid; i < 1024; i += 256) {
        int r = i >> 3, c = i & 7;
        *reinterpret_cast<uint4*>(smc + QO + swz(r, c)) =
            *reinterpret_cast<const uint4*>(qg + bho + (size_t)(q0 + r) * 64 + c * 8);
    }

    auto issue = [&](int t, int stg) {
        const size_t o = bho + (size_t)t * 128 * 64;
        uint32_t base = sb + (uint32_t)stg * STG;
#pragma unroll
        for (int i = tid; i < 1024; i += 256) {
            int r = i >> 3, c = i & 7;
            uint32_t off = swz(r, c);
            size_t g = o + (size_t)r * 64 + c * 8;
            cp16(base + KO + off, kg + g);
            cp16(base + VO + off, vg + g);
        }
    };
    issue(0, 0); CP_COMMIT();
    __syncthreads();   // Q visible

    uint32_t aq[4][4];
    {
        int rr = 16 * w + (lane & 7) + ((lane >> 3) & 1) * 8;
#pragma unroll
        for (int ks = 0; ks < 4; ks++) {
            int cc = 2 * ks + (lane >> 4);
            ldsm4(aq[ks][0], aq[ks][1], aq[ks][2], aq[ks][3], sb + QO + swz(rr, cc));
        }
    }

    float O[8][4] = {};
    float l0 = 0.f, l1 = 0.f;
    const int rg = 16 * w + (lane >> 2);
    const int qi0 = q0 + rg, qi1 = qi0 + 8;

    for (int t = 0; t < 16; t++) {
        if (t + 1 < 16) issue(t + 1, (t + 1) & 1);
        CP_COMMIT();
        CP_WAIT1();
        __syncthreads();

        const uint32_t stgb = sb + (uint32_t)(t & 1) * STG;
        const uint32_t Ks = stgb + KO, Vs = stgb + VO;

        uint32_t ep[16][2];
        // S = Q @ K^T in two 64-col halves (register pressure cap)
#pragma unroll
        for (int half = 0; half < 2; half++) {
            float S[8][4] = {};
#pragma unroll
            for (int ks = 0; ks < 4; ks++) {
#pragma unroll
                for (int ntp = 0; ntp < 4; ntp++) {
                    uint32_t b0, b1, b2, b3;
                    int rr = 16 * (4 * half + ntp) + (lane & 7) + ((lane >> 4) ? 8 : 0);
                    int cc = 2 * ks + ((lane >> 3) & 1);
                    ldsm4(b0, b1, b2, b3, Ks + swz(rr, cc));
                    mma_f16(S[2 * ntp],     aq[ks], b0, b1);
                    mma_f16(S[2 * ntp + 1], aq[ks], b2, b3);
                }
            }
#pragma unroll
            for (int s = 0; s < 8; s++) {
                int nt = 8 * half + s;
                int jc = t * 128 + 8 * nt + 2 * (lane & 3);
                float e0 = (jc     == qi0) ? 0.f : __expf(S[s][0] * scale);
                float e1 = (jc + 1 == qi0) ? 0.f : __expf(S[s][1] * scale);
                float e2 = (jc     == qi1) ? 0.f : __expf(S[s][2] * scale);
                float e3 = (jc + 1 == qi1) ? 0.f : __expf(S[s][3] * scale);
                l0 += e0 + e1;
                l1 += e2 + e3;
                ep[nt][0] = pkh(e0, e1);
                ep[nt][1] = pkh(e2, e3);
            }
        }

        // O += P @ V
#pragma unroll
        for (int ks = 0; ks < 8; ks++) {
            uint32_t ap[4] = { ep[2 * ks][0], ep[2 * ks][1],
                               ep[2 * ks + 1][0], ep[2 * ks + 1][1] };
#pragma unroll
            for (int ntp = 0; ntp < 4; ntp++) {
                uint32_t b0, b1, b2, b3;
                int rr = 16 * ks + (lane & 7) + ((lane >> 3) & 1) * 8;
                int cc = 2 * ntp + (lane >> 4);
                ldsm4t(b0, b1, b2, b3, Vs + swz(rr, cc));
                mma_f16(O[2 * ntp],     ap, b0, b1);
                mma_f16(O[2 * ntp + 1], ap, b2, b3);
            }
        }
        __syncthreads();
    }

    l0 += __shfl_xor_sync(0xffffffffu, l0, 1);
    l0 += __shfl_xor_sync(0xffffffffu, l0, 2);
    l1 += __shfl_xor_sync(0xffffffffu, l1, 1);
    l1 += __shfl_xor_sync(0xffffffffu, l1, 2);
    const float inv0 = 1.f / l0, inv1 = 1.f / l1;

#pragma unroll
    for (int i = 0; i < 2; i++) {
        const float inv = i ? inv1 : inv0;
        const size_t gm = (size_t)(b * 2048 + q0 + rg + i * 8);
#pragma unroll
        for (int nt = 0; nt < 8; nt++) {
            const int d = 8 * nt + 2 * (lane & 3);
            size_t idx = gm * INNER + h * DHEAD + d;
            *reinterpret_cast<uint32_t*>(aout + idx) =
                pkh(O[nt][2 * i] * inv, O[nt][2 * i + 1] * inv);
        }
    }
}

// ---------------- launch -----------------------------------------------------
extern "C" void kernel_launch(void* const* d_in, const int* in_sizes, int n_in,
                              void* d_out, int out_size) {
    const float* x        = (const float*)d_in[0];
    const float* W_qkv    = (const float*)d_in[1];
    const float* log_temp = (const float*)d_in[2];
    const float* W_out    = (const float*)d_in[3];
    const float* b_out    = (const float*)d_in[4];
    float* out = (float*)d_out;

    __half *xh, *wq, *wo, *q, *k, *v, *a;
    cudaGetSymbolAddress((void**)&xh, g_x);
    cudaGetSymbolAddress((void**)&wq, g_wq);
    cudaGetSymbolAddress((void**)&wo, g_wo);
    cudaGetSymbolAddress((void**)&q, g_q);
    cudaGetSymbolAddress((void**)&k, g_k);
    cudaGetSymbolAddress((void**)&v, g_v);
    cudaGetSymbolAddress((void**)&a, g_a);

    const int GSM = 65536;   // 2 stages x 32KB
    const int ASM = 81920;   // 2 stages x 32KB + Q 16KB
    cudaFuncSetAttribute(gemm_mma<0>, cudaFuncAttributeMaxDynamicSharedMemorySize, GSM);
    cudaFuncSetAttribute(gemm_mma<1>, cudaFuncAttributeMaxDynamicSharedMemorySize, GSM);
    cudaFuncSetAttribute(attn_mma,    cudaFuncAttributeMaxDynamicSharedMemorySize, ASM);

    k_cast<<<(NROWS * DIMX + 255) / 256, 256>>>(x, xh, NROWS * DIMX);
    k_castT<<<(DIMX * 3 * INNER + 255) / 256, 256>>>(W_qkv, wq, DIMX, 3 * INNER);
    k_castT<<<(INNER * DIMX + 255) / 256, 256>>>(W_out, wo, INNER, DIMX);

    // 1) QKV projection (1-term fp16) -> q/k/v per-head layout
    gemm_mma<0><<<dim3(12, 64), 512, GSM>>>(xh, wq, DIMX, q, k, v, nullptr, nullptr);
    // 2) attention
    attn_mma<<<dim3(SSEQ / 128, BB * HEADS), 256, ASM>>>(q, k, v, log_temp, a);
    // 3) output projection (1-term) + bias -> fp32
    gemm_mma<1><<<dim3(4, 64), 512, GSM>>>(a, wo, INNER,
                                           nullptr, nullptr, nullptr, b_out, out);
}

// round 11
// speedup vs baseline: 1.3028x; 1.0567x over previous
#include <cuda_runtime.h>
#include <cuda_fp16.h>
#include <cstdint>
#include <math.h>

#define BB 4
#define SSEQ 2048
#define DIMX 512
#define HEADS 8
#define DHEAD 64
#define INNER 512
#define NROWS (BB * SSEQ)   // 8192

#define NX  (NROWS * DIMX)        // 4194304
#define NWQ (3 * INNER * DIMX)    // 786432
#define NWO (DIMX * INNER)        // 262144

// ---------------- device scratch -------------------------------------------
__device__ __half g_x[NX];
__device__ __half g_wq[NWQ];   // W_qkv^T  [1536][512]
__device__ __half g_wo[NWO];   // W_out^T  [512][512]
__device__ __half g_q[NROWS * INNER];   // [bh][s][64]
__device__ __half g_k[NROWS * INNER];
__device__ __half g_v[NROWS * INNER];
__device__ __half g_a[NROWS * INNER];   // [b*s][512]

// ---------------- helpers ---------------------------------------------------
__device__ __forceinline__ uint32_t smem_u32(const void* p) {
    uint32_t a;
    asm("{ .reg .u64 t; cvta.to.shared.u64 t, %1; cvt.u32.u64 %0, t; }" : "=r"(a) : "l"(p));
    return a;
}
__device__ __forceinline__ void ldsm4(uint32_t& r0, uint32_t& r1, uint32_t& r2,
                                      uint32_t& r3, uint32_t addr) {
    asm volatile("ldmatrix.sync.aligned.m8n8.x4.shared.b16 {%0,%1,%2,%3}, [%4];"
                 : "=r"(r0), "=r"(r1), "=r"(r2), "=r"(r3) : "r"(addr));
}
__device__ __forceinline__ void ldsm4t(uint32_t& r0, uint32_t& r1, uint32_t& r2,
                                       uint32_t& r3, uint32_t addr) {
    asm volatile("ldmatrix.sync.aligned.m8n8.x4.trans.shared.b16 {%0,%1,%2,%3}, [%4];"
                 : "=r"(r0), "=r"(r1), "=r"(r2), "=r"(r3) : "r"(addr));
}
__device__ __forceinline__ void mma_f16(float* c, const uint32_t a[4],
                                        uint32_t b0, uint32_t b1) {
    asm volatile(
        "mma.sync.aligned.m16n8k16.row.col.f32.f16.f16.f32 "
        "{%0,%1,%2,%3}, {%4,%5,%6,%7}, {%8,%9}, {%0,%1,%2,%3};"
        : "+f"(c[0]), "+f"(c[1]), "+f"(c[2]), "+f"(c[3])
        : "r"(a[0]), "r"(a[1]), "r"(a[2]), "r"(a[3]), "r"(b0), "r"(b1));
}
__device__ __forceinline__ void cp16(uint32_t dst, const void* src) {
    asm volatile("cp.async.cg.shared.global [%0], [%1], 16;" :: "r"(dst), "l"(src));
}
#define CP_COMMIT() asm volatile("cp.async.commit_group;" ::: "memory")
#define CP_WAIT1()  asm volatile("cp.async.wait_group 1;" ::: "memory")

__device__ __forceinline__ uint32_t pkh(float a, float b) {   // a in low half
    __half2 x = __floats2half2_rn(a, b);
    return *reinterpret_cast<uint32_t*>(&x);
}
// 16B-chunk swizzle within 128B rows (conflict-free ldmatrix)
__device__ __forceinline__ uint32_t swz(int r, int c) {
    return (uint32_t)r * 128u + (uint32_t)((c ^ (r & 7)) & 7) * 16u;
}

// ---------------- single fused convert kernel --------------------------------
__global__ void k_convert(const float* __restrict__ x, const float* __restrict__ Wq,
                          const float* __restrict__ Wo,
                          __half* __restrict__ xo, __half* __restrict__ wqo,
                          __half* __restrict__ woo) {
    int i = blockIdx.x * blockDim.x + threadIdx.x;
    if (i < NX) {
        xo[i] = __float2half_rn(x[i]);
    } else if (i < NX + NWQ) {
        int j = i - NX;
        int n = j >> 9, k = j & 511;                 // out [n][k], K=512
        wqo[j] = __float2half_rn(Wq[(size_t)k * 1536 + n]);
    } else if (i < NX + NWQ + NWO) {
        int j = i - NX - NWQ;
        int n = j >> 9, k = j & 511;
        woo[j] = __float2half_rn(Wo[(size_t)k * 512 + n]);
    }
}

// ---------------- fp16 GEMM, 512 threads, k-chunk 128 ------------------------
// tile 128x128, warp grid 4x4, warp tile 32x32.
// Stage 64KB: A0(cols0-63) | A1 | B0 | B1, each 16KB of 128B swizzled rows.
// MODE 0: -> q/k/v fp16 per-head layout;  MODE 1: fp32 + bias.
template <int MODE>
__global__ void __launch_bounds__(512, 1)
gemm_mma(const __half* __restrict__ Ah, const __half* __restrict__ Bh, int Kd,
         __half* __restrict__ q, __half* __restrict__ k, __half* __restrict__ v,
         const float* __restrict__ bias, float* __restrict__ outp) {
    extern __shared__ char smc[];
    const uint32_t sb = smem_u32(smc);
    const int tid = threadIdx.x, w = tid >> 5, lane = tid & 31;
    const int m0 = blockIdx.y * 128, n0 = blockIdx.x * 128;
    const int wm = w & 3, wn = w >> 2;
    const uint32_t STG = 65536;

    float acc[2][4][4] = {};

    auto issue = [&](int kc, int stg) {
        uint32_t base = sb + (uint32_t)stg * STG;
#pragma unroll
        for (int i = tid; i < 2048; i += 512) {
            int r = i >> 4, c = i & 15;                 // 128 rows x 16 chunks
            uint32_t off = (uint32_t)(c >> 3) * 16384u + swz(r, c & 7);
            cp16(base + off,          Ah + (size_t)(m0 + r) * Kd + kc + c * 8);
            cp16(base + 32768 + off,  Bh + (size_t)(n0 + r) * Kd + kc + c * 8);
        }
    };

    const int nch = Kd / 128;   // 4
    issue(0, 0); CP_COMMIT();

    for (int kc = 0; kc < nch; kc++) {
        if (kc + 1 < nch) issue((kc + 1) * 128, (kc + 1) & 1);
        CP_COMMIT();
        CP_WAIT1();
        __syncthreads();

        const uint32_t As = sb + (uint32_t)(kc & 1) * STG;
        const uint32_t Bs = As + 32768;
#pragma unroll
        for (int ks = 0; ks < 8; ks++) {
            const uint32_t Ab = As + (uint32_t)(ks >> 2) * 16384u;
            const uint32_t Bb = Bs + (uint32_t)(ks >> 2) * 16384u;
            const int kk = ks & 3;
            uint32_t ah[2][4];
#pragma unroll
            for (int mt = 0; mt < 2; mt++) {
                int rr = 32 * wm + 16 * mt + (lane & 7) + ((lane >> 3) & 1) * 8;
                int cc = 2 * kk + (lane >> 4);
                ldsm4(ah[mt][0], ah[mt][1], ah[mt][2], ah[mt][3], Ab + swz(rr, cc));
            }
#pragma unroll
            for (int ntp = 0; ntp < 2; ntp++) {
                int rr = 32 * wn + 16 * ntp + (lane & 7) + ((lane >> 4) ? 8 : 0);
                int cc = 2 * kk + ((lane >> 3) & 1);
                uint32_t b0, b1, b2, b3;
                ldsm4(b0, b1, b2, b3, Bb + swz(rr, cc));
#pragma unroll
                for (int mt = 0; mt < 2; mt++) {
                    mma_f16(acc[mt][2 * ntp],     ah[mt], b0, b1);
                    mma_f16(acc[mt][2 * ntp + 1], ah[mt], b2, b3);
                }
            }
        }
        __syncthreads();
    }

    // epilogue
#pragma unroll
    for (int mt = 0; mt < 2; mt++) {
#pragma unroll
        for (int i = 0; i < 2; i++) {
            const int gm = m0 + 32 * wm + 16 * mt + (lane >> 2) + i * 8;
#pragma unroll
            for (int nt = 0; nt < 4; nt++) {
                const int gn = n0 + 32 * wn + 8 * nt + 2 * (lane & 3);
                float v0 = acc[mt][nt][2 * i], v1 = acc[mt][nt][2 * i + 1];
                if (MODE == 0) {
                    const int seg = gn >> 9, nn = gn & 511;
                    const int h = nn >> 6, d = nn & 63;
                    const int bI = gm >> 11, s = gm & 2047;
                    size_t idx = ((size_t)((bI * 8 + h) * 2048 + s)) * 64 + d;
                    __half* dst = (seg == 0) ? q : (seg == 1) ? k : v;
                    *reinterpret_cast<uint32_t*>(dst + idx) = pkh(v0, v1);
                } else {
                    float2 o = make_float2(v0 + bias[gn], v1 + bias[gn + 1]);
                    *reinterpret_cast<float2*>(outp + (size_t)gm * 512 + gn) = o;
                }
            }
        }
    }
}

// ---------------- attention: fp16 HMMA flash (unchanged from R10) ------------
__global__ void __launch_bounds__(256, 2)
attn_mma(const __half* __restrict__ qg, const __half* __restrict__ kg,
         const __half* __restrict__ vg, const float* __restrict__ log_temp,
         __half* __restrict__ aout) {
    extern __shared__ char smc[];
    const uint32_t sb = smem_u32(smc);
    const int tid = threadIdx.x, w = tid >> 5, lane = tid & 31;
    const int q0 = blockIdx.x * 128;
    const int bh = blockIdx.y, b = bh >> 3, h = bh & 7;
    const uint32_t KO = 0, VO = 16384, STG = 32768, QO = 65536;

    const float scale = __expf(*log_temp) * 1.4426950408889634f;  // fold log2(e)
    const size_t bho = (size_t)bh * 2048 * 64;

    // Q -> smem
#pragma unroll
    for (int i = tid; i < 1024; i += 256) {
        int r = i >> 3, c = i & 7;
        *reinterpret_cast<uint4*>(smc + QO + swz(r, c)) =
            *reinterpret_cast<const uint4*>(qg + bho + (size_t)(q0 + r) * 64 + c * 8);
    }

    auto issue = [&](int t, int stg) {
        const size_t o = bho + (size_t)t * 128 * 64;
        uint32_t base = sb + (uint32_t)stg * STG;
#pragma unroll
        for (int i = tid; i < 1024; i += 256) {
            int r = i >> 3, c = i & 7;
            uint32_t off = swz(r, c);
            size_t g = o + (size_t)r * 64 + c * 8;
            cp16(base + KO + off, kg + g);
            cp16(base + VO + off, vg + g);
        }
    };
    issue(0, 0); CP_COMMIT();
    __syncthreads();   // Q visible

    uint32_t aq[4][4];
    {
        int rr = 16 * w + (lane & 7) + ((lane >> 3) & 1) * 8;
#pragma unroll
        for (int ks = 0; ks < 4; ks++) {
            int cc = 2 * ks + (lane >> 4);
            ldsm4(aq[ks][0], aq[ks][1], aq[ks][2], aq[ks][3], sb + QO + swz(rr, cc));
        }
    }

    float O[8][4] = {};
    float l0 = 0.f, l1 = 0.f;
    const int rg = 16 * w + (lane >> 2);
    const int qi0 = q0 + rg, qi1 = qi0 + 8;

    for (int t = 0; t < 16; t++) {
        if (t + 1 < 16) issue(t + 1, (t + 1) & 1);
        CP_COMMIT();
        CP_WAIT1();
        __syncthreads();

        const uint32_t stgb = sb + (uint32_t)(t & 1) * STG;
        const uint32_t Ks = stgb + KO, Vs = stgb + VO;

        uint32_t ep[16][2];
#pragma unroll
        for (int half = 0; half < 2; half++) {
            float S[8][4] = {};
#pragma unroll
            for (int ks = 0; ks < 4; ks++) {
#pragma unroll
                for (int ntp = 0; ntp < 4; ntp++) {
                    uint32_t b0, b1, b2, b3;
                    int rr = 16 * (4 * half + ntp) + (lane & 7) + ((lane >> 4) ? 8 : 0);
                    int cc = 2 * ks + ((lane >> 3) & 1);
                    ldsm4(b0, b1, b2, b3, Ks + swz(rr, cc));
                    mma_f16(S[2 * ntp],     aq[ks], b0, b1);
                    mma_f16(S[2 * ntp + 1], aq[ks], b2, b3);
                }
            }
#pragma unroll
            for (int s = 0; s < 8; s++) {
                int nt = 8 * half + s;
                int jc = t * 128 + 8 * nt + 2 * (lane & 3);
                float e0 = (jc     == qi0) ? 0.f : exp2f(S[s][0] * scale);
                float e1 = (jc + 1 == qi0) ? 0.f : exp2f(S[s][1] * scale);
                float e2 = (jc     == qi1) ? 0.f : exp2f(S[s][2] * scale);
                float e3 = (jc + 1 == qi1) ? 0.f : exp2f(S[s][3] * scale);
                l0 += e0 + e1;
                l1 += e2 + e3;
                ep[nt][0] = pkh(e0, e1);
                ep[nt][1] = pkh(e2, e3);
            }
        }

        // O += P @ V
#pragma unroll
        for (int ks = 0; ks < 8; ks++) {
            uint32_t ap[4] = { ep[2 * ks][0], ep[2 * ks][1],
                               ep[2 * ks + 1][0], ep[2 * ks + 1][1] };
#pragma unroll
            for (int ntp = 0; ntp < 4; ntp++) {
                uint32_t b0, b1, b2, b3;
                int rr = 16 * ks + (lane & 7) + ((lane >> 3) & 1) * 8;
                int cc = 2 * ntp + (lane >> 4);
                ldsm4t(b0, b1, b2, b3, Vs + swz(rr, cc));
                mma_f16(O[2 * ntp],     ap, b0, b1);
                mma_f16(O[2 * ntp + 1], ap, b2, b3);
            }
        }
        __syncthreads();
    }

    l0 += __shfl_xor_sync(0xffffffffu, l0, 1);
    l0 += __shfl_xor_sync(0xffffffffu, l0, 2);
    l1 += __shfl_xor_sync(0xffffffffu, l1, 1);
    l1 += __shfl_xor_sync(0xffffffffu, l1, 2);
    const float inv0 = 1.f / l0, inv1 = 1.f / l1;

#pragma unroll
    for (int i = 0; i < 2; i++) {
        const float inv = i ? inv1 : inv0;
        const size_t gm = (size_t)(b * 2048 + q0 + rg + i * 8);
#pragma unroll
        for (int nt = 0; nt < 8; nt++) {
            const int d = 8 * nt + 2 * (lane & 3);
            size_t idx = gm * INNER + h * DHEAD + d;
            *reinterpret_cast<uint32_t*>(aout + idx) =
                pkh(O[nt][2 * i] * inv, O[nt][2 * i + 1] * inv);
        }
    }
}

// ---------------- launch -----------------------------------------------------
extern "C" void kernel_launch(void* const* d_in, const int* in_sizes, int n_in,
                              void* d_out, int out_size) {
    const float* x        = (const float*)d_in[0];
    const float* W_qkv    = (const float*)d_in[1];
    const float* log_temp = (const float*)d_in[2];
    const float* W_out    = (const float*)d_in[3];
    const float* b_out    = (const float*)d_in[4];
    float* out = (float*)d_out;

    __half *xh, *wq, *wo, *q, *k, *v, *a;
    cudaGetSymbolAddress((void**)&xh, g_x);
    cudaGetSymbolAddress((void**)&wq, g_wq);
    cudaGetSymbolAddress((void**)&wo, g_wo);
    cudaGetSymbolAddress((void**)&q, g_q);
    cudaGetSymbolAddress((void**)&k, g_k);
    cudaGetSymbolAddress((void**)&v, g_v);
    cudaGetSymbolAddress((void**)&a, g_a);

    const int GSM = 131072;  // 2 stages x 64KB
    const int ASM = 81920;   // 2 stages x 32KB + Q 16KB
    cudaFuncSetAttribute(gemm_mma<0>, cudaFuncAttributeMaxDynamicSharedMemorySize, GSM);
    cudaFuncSetAttribute(gemm_mma<1>, cudaFuncAttributeMaxDynamicSharedMemorySize, GSM);
    cudaFuncSetAttribute(attn_mma,    cudaFuncAttributeMaxDynamicSharedMemorySize, ASM);

    // fused converts (x cast + both weight transpose-casts)
    k_convert<<<(NX + NWQ + NWO + 255) / 256, 256>>>(x, W_qkv, W_out, xh, wq, wo);

    // 1) QKV projection (1-term fp16, k-chunk 128)
    gemm_mma<0><<<dim3(12, 64), 512, GSM>>>(xh, wq, DIMX, q, k, v, nullptr, nullptr);
    // 2) attention
    attn_mma<<<dim3(SSEQ / 128, BB * HEADS), 256, ASM>>>(q, k, v, log_temp, a);
    // 3) output projection + bias -> fp32
    gemm_mma<1><<<dim3(4, 64), 512, GSM>>>(a, wo, INNER,
                                           nullptr, nullptr, nullptr, b_out, out);
}

// round 12
// speedup vs baseline: 1.4113x; 1.0833x over previous
#include <cuda_runtime.h>
#include <cuda_fp16.h>
#include <cstdint>
#include <math.h>

#define BB 4
#define SSEQ 2048
#define DIMX 512
#define HEADS 8
#define DHEAD 64
#define INNER 512
#define NROWS (BB * SSEQ)   // 8192
#define NX  (NROWS * DIMX)

// ---------------- device scratch -------------------------------------------
__device__ __half g_x[NX];
__device__ __half g_wq[3 * INNER * DIMX];   // W_qkv^T [1536][512]
__device__ __half g_wo[DIMX * INNER];       // W_out^T [512][512]
__device__ __half g_q[NROWS * INNER];       // [bh][s][64], pre-scaled by exp(log_temp)*log2e
__device__ __half g_k[NROWS * INNER];
__device__ __half g_v[NROWS * INNER];
__device__ __half g_a[NROWS * INNER];       // [b*s][512]

// ---------------- helpers ---------------------------------------------------
__device__ __forceinline__ uint32_t smem_u32(const void* p) {
    uint32_t a;
    asm("{ .reg .u64 t; cvta.to.shared.u64 t, %1; cvt.u32.u64 %0, t; }" : "=r"(a) : "l"(p));
    return a;
}
__device__ __forceinline__ void ldsm4(uint32_t& r0, uint32_t& r1, uint32_t& r2,
                                      uint32_t& r3, uint32_t addr) {
    asm volatile("ldmatrix.sync.aligned.m8n8.x4.shared.b16 {%0,%1,%2,%3}, [%4];"
                 : "=r"(r0), "=r"(r1), "=r"(r2), "=r"(r3) : "r"(addr));
}
__device__ __forceinline__ void ldsm4t(uint32_t& r0, uint32_t& r1, uint32_t& r2,
                                       uint32_t& r3, uint32_t addr) {
    asm volatile("ldmatrix.sync.aligned.m8n8.x4.trans.shared.b16 {%0,%1,%2,%3}, [%4];"
                 : "=r"(r0), "=r"(r1), "=r"(r2), "=r"(r3) : "r"(addr));
}
__device__ __forceinline__ void mma_f16(float* c, const uint32_t a[4],
                                        uint32_t b0, uint32_t b1) {
    asm volatile(
        "mma.sync.aligned.m16n8k16.row.col.f32.f16.f16.f32 "
        "{%0,%1,%2,%3}, {%4,%5,%6,%7}, {%8,%9}, {%0,%1,%2,%3};"
        : "+f"(c[0]), "+f"(c[1]), "+f"(c[2]), "+f"(c[3])
        : "r"(a[0]), "r"(a[1]), "r"(a[2]), "r"(a[3]), "r"(b0), "r"(b1));
}
__device__ __forceinline__ void cp16(uint32_t dst, const void* src) {
    asm volatile("cp.async.cg.shared.global [%0], [%1], 16;" :: "r"(dst), "l"(src));
}
#define CP_COMMIT() asm volatile("cp.async.commit_group;" ::: "memory")
#define CP_WAIT1()  asm volatile("cp.async.wait_group 1;" ::: "memory")

__device__ __forceinline__ uint32_t pkh(float a, float b) {   // a in low half
    __half2 x = __floats2half2_rn(a, b);
    return *reinterpret_cast<uint32_t*>(&x);
}
// 16B-chunk swizzle within 128B rows (conflict-free ldmatrix)
__device__ __forceinline__ uint32_t swz(int r, int c) {
    return (uint32_t)r * 128u + (uint32_t)((c ^ (r & 7)) & 7) * 16u;
}

// ---------------- convert kernels -------------------------------------------
__global__ void k_cast(const float* __restrict__ in, __half* __restrict__ o, int n) {
    int i = blockIdx.x * blockDim.x + threadIdx.x;
    if (i < n) o[i] = __float2half_rn(in[i]);
}
// in [K][N] fp32 -> out [N][K] fp16, coalesced both sides via smem tile
__global__ void k_tcast(const float* __restrict__ in, __half* __restrict__ o,
                        int K, int N) {
    __shared__ float t[32][33];
    const int bn = blockIdx.x * 32, bk = blockIdx.y * 32;
    const int tx = threadIdx.x, ty = threadIdx.y;   // 32 x 8
#pragma unroll
    for (int j = 0; j < 32; j += 8)
        t[ty + j][tx] = in[(size_t)(bk + ty + j) * N + bn + tx];
    __syncthreads();
#pragma unroll
    for (int j = 0; j < 32; j += 8)
        o[(size_t)(bn + ty + j) * K + bk + tx] = __float2half_rn(t[tx][ty + j]);
}

// ---------------- fp16 GEMM, 256 threads, 2 CTAs/SM --------------------------
// tile 128x128, warp grid 4x2, warp tile 32x64, k-chunk 64, 2x32KB stages.
// MODE 0: -> q/k/v fp16 per-head layout (q pre-scaled);  MODE 1: fp32 + bias.
template <int MODE>
__global__ void __launch_bounds__(256, 2)
gemm_mma(const __half* __restrict__ Ah, const __half* __restrict__ Bh, int Kd,
         __half* __restrict__ q, __half* __restrict__ k, __half* __restrict__ v,
         const float* __restrict__ log_temp,
         const float* __restrict__ bias, float* __restrict__ outp) {
    extern __shared__ char smc[];
    const uint32_t sb = smem_u32(smc);
    const int tid = threadIdx.x, w = tid >> 5, lane = tid & 31;
    const int m0 = blockIdx.y * 128, n0 = blockIdx.x * 128;
    const int wm = w & 3, wn = w >> 2;
    const uint32_t STG = 32768;   // A 16K | B 16K

    float acc[2][8][4] = {};

    auto issue = [&](int kc, int stg) {
        uint32_t base = sb + (uint32_t)stg * STG;
#pragma unroll
        for (int i = tid; i < 1024; i += 256) {
            int r = i >> 3, c = i & 7;
            uint32_t off = swz(r, c);
            cp16(base + off,         Ah + (size_t)(m0 + r) * Kd + kc + c * 8);
            cp16(base + 16384 + off, Bh + (size_t)(n0 + r) * Kd + kc + c * 8);
        }
    };

    const int nch = Kd / 64;
    issue(0, 0); CP_COMMIT();

    for (int kc = 0; kc < nch; kc++) {
        if (kc + 1 < nch) issue((kc + 1) * 64, (kc + 1) & 1);
        CP_COMMIT();
        CP_WAIT1();
        __syncthreads();

        const uint32_t As = sb + (uint32_t)(kc & 1) * STG;
        const uint32_t Bs = As + 16384;
#pragma unroll
        for (int ks = 0; ks < 4; ks++) {
            uint32_t ah[2][4];
#pragma unroll
            for (int mt = 0; mt < 2; mt++) {
                int rr = 32 * wm + 16 * mt + (lane & 7) + ((lane >> 3) & 1) * 8;
                int cc = 2 * ks + (lane >> 4);
                ldsm4(ah[mt][0], ah[mt][1], ah[mt][2], ah[mt][3], As + swz(rr, cc));
            }
#pragma unroll
            for (int nb = 0; nb < 4; nb++) {
                int rr = 64 * wn + 16 * nb + (lane & 7) + ((lane >> 4) ? 8 : 0);
                int cc = 2 * ks + ((lane >> 3) & 1);
                uint32_t b0, b1, b2, b3;
                ldsm4(b0, b1, b2, b3, Bs + swz(rr, cc));
#pragma unroll
                for (int mt = 0; mt < 2; mt++) {
                    mma_f16(acc[mt][2 * nb],     ah[mt], b0, b1);
                    mma_f16(acc[mt][2 * nb + 1], ah[mt], b2, b3);
                }
            }
        }
        __syncthreads();
    }

    // epilogue
    const float qscale = (MODE == 0) ? __expf(*log_temp) * 1.4426950408889634f : 1.f;
#pragma unroll
    for (int mt = 0; mt < 2; mt++) {
#pragma unroll
        for (int i = 0; i < 2; i++) {
            const int gm = m0 + 32 * wm + 16 * mt + (lane >> 2) + i * 8;
#pragma unroll
            for (int nt = 0; nt < 8; nt++) {
                const int gn = n0 + 64 * wn + 8 * nt + 2 * (lane & 3);
                float v0 = acc[mt][nt][2 * i], v1 = acc[mt][nt][2 * i + 1];
                if (MODE == 0) {
                    const int seg = gn >> 9, nn = gn & 511;
                    const int h = nn >> 6, d = nn & 63;
                    const int bI = gm >> 11, s = gm & 2047;
                    size_t idx = ((size_t)((bI * 8 + h) * 2048 + s)) * 64 + d;
                    if (seg == 0) { v0 *= qscale; v1 *= qscale; }
                    __half* dst = (seg == 0) ? q : (seg == 1) ? k : v;
                    *reinterpret_cast<uint32_t*>(dst + idx) = pkh(v0, v1);
                } else {
                    float2 o = make_float2(v0 + bias[gn], v1 + bias[gn + 1]);
                    *reinterpret_cast<float2*>(outp + (size_t)gm * 512 + gn) = o;
                }
            }
        }
    }
}

// ---------------- attention: fp16 HMMA flash (scale pre-folded into q) -------
__global__ void __launch_bounds__(256, 2)
attn_mma(const __half* __restrict__ qg, const __half* __restrict__ kg,
         const __half* __restrict__ vg, __half* __restrict__ aout) {
    extern __shared__ char smc[];
    const uint32_t sb = smem_u32(smc);
    const int tid = threadIdx.x, w = tid >> 5, lane = tid & 31;
    const int q0 = blockIdx.x * 128;
    const int bh = blockIdx.y, b = bh >> 3, h = bh & 7;
    const uint32_t KO = 0, VO = 16384, STG = 32768, QO = 65536;

    const size_t bho = (size_t)bh * 2048 * 64;

    // Q -> smem
#pragma unroll
    for (int i = tid; i < 1024; i += 256) {
        int r = i >> 3, c = i & 7;
        *reinterpret_cast<uint4*>(smc + QO + swz(r, c)) =
            *reinterpret_cast<const uint4*>(qg + bho + (size_t)(q0 + r) * 64 + c * 8);
    }

    auto issue = [&](int t, int stg) {
        const size_t o = bho + (size_t)t * 128 * 64;
        uint32_t base = sb + (uint32_t)stg * STG;
#pragma unroll
        for (int i = tid; i < 1024; i += 256) {
            int r = i >> 3, c = i & 7;
            uint32_t off = swz(r, c);
            size_t g = o + (size_t)r * 64 + c * 8;
            cp16(base + KO + off, kg + g);
            cp16(base + VO + off, vg + g);
        }
    };
    issue(0, 0); CP_COMMIT();
    __syncthreads();   // Q visible

    uint32_t aq[4][4];
    {
        int rr = 16 * w + (lane & 7) + ((lane >> 3) & 1) * 8;
#pragma unroll
        for (int ks = 0; ks < 4; ks++) {
            int cc = 2 * ks + (lane >> 4);
            ldsm4(aq[ks][0], aq[ks][1], aq[ks][2], aq[ks][3], sb + QO + swz(rr, cc));
        }
    }

    float O[8][4] = {};
    float l0 = 0.f, l1 = 0.f;
    const int rg = 16 * w + (lane >> 2);
    const int qi0 = q0 + rg, qi1 = qi0 + 8;

    for (int t = 0; t < 16; t++) {
        if (t + 1 < 16) issue(t + 1, (t + 1) & 1);
        CP_COMMIT();
        CP_WAIT1();
        __syncthreads();

        const uint32_t stgb = sb + (uint32_t)(t & 1) * STG;
        const uint32_t Ks = stgb + KO, Vs = stgb + VO;

        uint32_t ep[16][2];
#pragma unroll
        for (int half = 0; half < 2; half++) {
            float S[8][4] = {};
#pragma unroll
            for (int ks = 0; ks < 4; ks++) {
#pragma unroll
                for (int ntp = 0; ntp < 4; ntp++) {
                    uint32_t b0, b1, b2, b3;
                    int rr = 16 * (4 * half + ntp) + (lane & 7) + ((lane >> 4) ? 8 : 0);
                    int cc = 2 * ks + ((lane >> 3) & 1);
                    ldsm4(b0, b1, b2, b3, Ks + swz(rr, cc));
                    mma_f16(S[2 * ntp],     aq[ks], b0, b1);
                    mma_f16(S[2 * ntp + 1], aq[ks], b2, b3);
                }
            }
#pragma unroll
            for (int s = 0; s < 8; s++) {
                int nt = 8 * half + s;
                int jc = t * 128 + 8 * nt + 2 * (lane & 3);
                float e0 = (jc     == qi0) ? 0.f : exp2f(S[s][0]);
                float e1 = (jc + 1 == qi0) ? 0.f : exp2f(S[s][1]);
                float e2 = (jc     == qi1) ? 0.f : exp2f(S[s][2]);
                float e3 = (jc + 1 == qi1) ? 0.f : exp2f(S[s][3]);
                l0 += e0 + e1;
                l1 += e2 + e3;
                ep[nt][0] = pkh(e0, e1);
                ep[nt][1] = pkh(e2, e3);
            }
        }

        // O += P @ V
#pragma unroll
        for (int ks = 0; ks < 8; ks++) {
            uint32_t ap[4] = { ep[2 * ks][0], ep[2 * ks][1],
                               ep[2 * ks + 1][0], ep[2 * ks + 1][1] };
#pragma unroll
            for (int ntp = 0; ntp < 4; ntp++) {
                uint32_t b0, b1, b2, b3;
                int rr = 16 * ks + (lane & 7) + ((lane >> 3) & 1) * 8;
                int cc = 2 * ntp + (lane >> 4);
                ldsm4t(b0, b1, b2, b3, Vs + swz(rr, cc));
                mma_f16(O[2 * ntp],     ap, b0, b1);
                mma_f16(O[2 * ntp + 1], ap, b2, b3);
            }
        }
        __syncthreads();
    }

    l0 += __shfl_xor_sync(0xffffffffu, l0, 1);
    l0 += __shfl_xor_sync(0xffffffffu, l0, 2);
    l1 += __shfl_xor_sync(0xffffffffu, l1, 1);
    l1 += __shfl_xor_sync(0xffffffffu, l1, 2);
    const float inv0 = 1.f / l0, inv1 = 1.f / l1;

#pragma unroll
    for (int i = 0; i < 2; i++) {
        const float inv = i ? inv1 : inv0;
        const size_t gm = (size_t)(b * 2048 + q0 + rg + i * 8);
#pragma unroll
        for (int nt = 0; nt < 8; nt++) {
            const int d = 8 * nt + 2 * (lane & 3);
            size_t idx = gm * INNER + h * DHEAD + d;
            *reinterpret_cast<uint32_t*>(aout + idx) =
                pkh(O[nt][2 * i] * inv, O[nt][2 * i + 1] * inv);
        }
    }
}

// ---------------- launch -----------------------------------------------------
extern "C" void kernel_launch(void* const* d_in, const int* in_sizes, int n_in,
                              void* d_out, int out_size) {
    const float* x        = (const float*)d_in[0];
    const float* W_qkv    = (const float*)d_in[1];
    const float* log_temp = (const float*)d_in[2];
    const float* W_out    = (const float*)d_in[3];
    const float* b_out    = (const float*)d_in[4];
    float* out = (float*)d_out;

    __half *xh, *wq, *wo, *q, *k, *v, *a;
    cudaGetSymbolAddress((void**)&xh, g_x);
    cudaGetSymbolAddress((void**)&wq, g_wq);
    cudaGetSymbolAddress((void**)&wo, g_wo);
    cudaGetSymbolAddress((void**)&q, g_q);
    cudaGetSymbolAddress((void**)&k, g_k);
    cudaGetSymbolAddress((void**)&v, g_v);
    cudaGetSymbolAddress((void**)&a, g_a);

    const int GSM = 65536;   // 2 stages x 32KB
    const int ASM = 81920;   // 2 stages x 32KB + Q 16KB
    cudaFuncSetAttribute(gemm_mma<0>, cudaFuncAttributeMaxDynamicSharedMemorySize, GSM);
    cudaFuncSetAttribute(gemm_mma<1>, cudaFuncAttributeMaxDynamicSharedMemorySize, GSM);
    cudaFuncSetAttribute(attn_mma,    cudaFuncAttributeMaxDynamicSharedMemorySize, ASM);

    // converts: coalesced cast + smem-tile transposes
    k_cast<<<(NX + 255) / 256, 256>>>(x, xh, NX);
    k_tcast<<<dim3(48, 16), dim3(32, 8)>>>(W_qkv, wq, DIMX, 3 * INNER);
    k_tcast<<<dim3(16, 16), dim3(32, 8)>>>(W_out, wo, INNER, DIMX);

    // 1) QKV projection (q pre-scaled by exp(log_temp)*log2e)
    gemm_mma<0><<<dim3(12, 64), 256, GSM>>>(xh, wq, DIMX, q, k, v,
                                            log_temp, nullptr, nullptr);
    // 2) attention
    attn_mma<<<dim3(SSEQ / 128, BB * HEADS), 256, ASM>>>(q, k, v, a);
    // 3) output projection + bias -> fp32
    gemm_mma<1><<<dim3(4, 64), 256, GSM>>>(a, wo, INNER, nullptr, nullptr, nullptr,
                                           nullptr, b_out, out);
}

// round 13
// speedup vs baseline: 1.4952x; 1.0595x over previous
#include <cuda_runtime.h>
#include <cuda_fp16.h>
#include <cstdint>
#include <math.h>

#define BB 4
#define SSEQ 2048
#define DIMX 512
#define HEADS 8
#define DHEAD 64
#define INNER 512
#define NROWS (BB * SSEQ)   // 8192
#define NX  (NROWS * DIMX)  // 4194304

// ---------------- device scratch -------------------------------------------
__device__ __half g_x[NX];
__device__ __half g_wq[3 * INNER * DIMX];   // W_qkv^T [1536][512]
__device__ __half g_wo[DIMX * INNER];       // W_out^T [512][512]
__device__ __half g_q[NROWS * INNER];       // [bh][s][64], pre-scaled
__device__ __half g_k[NROWS * INNER];
__device__ __half g_v[NROWS * INNER];
__device__ __half g_a[NROWS * INNER];       // [b*s][512]

// ---------------- helpers ---------------------------------------------------
__device__ __forceinline__ uint32_t smem_u32(const void* p) {
    uint32_t a;
    asm("{ .reg .u64 t; cvta.to.shared.u64 t, %1; cvt.u32.u64 %0, t; }" : "=r"(a) : "l"(p));
    return a;
}
__device__ __forceinline__ void ldsm4(uint32_t& r0, uint32_t& r1, uint32_t& r2,
                                      uint32_t& r3, uint32_t addr) {
    asm volatile("ldmatrix.sync.aligned.m8n8.x4.shared.b16 {%0,%1,%2,%3}, [%4];"
                 : "=r"(r0), "=r"(r1), "=r"(r2), "=r"(r3) : "r"(addr));
}
__device__ __forceinline__ void ldsm4t(uint32_t& r0, uint32_t& r1, uint32_t& r2,
                                       uint32_t& r3, uint32_t addr) {
    asm volatile("ldmatrix.sync.aligned.m8n8.x4.trans.shared.b16 {%0,%1,%2,%3}, [%4];"
                 : "=r"(r0), "=r"(r1), "=r"(r2), "=r"(r3) : "r"(addr));
}
__device__ __forceinline__ void mma_f16(float* c, const uint32_t a[4],
                                        uint32_t b0, uint32_t b1) {
    asm volatile(
        "mma.sync.aligned.m16n8k16.row.col.f32.f16.f16.f32 "
        "{%0,%1,%2,%3}, {%4,%5,%6,%7}, {%8,%9}, {%0,%1,%2,%3};"
        : "+f"(c[0]), "+f"(c[1]), "+f"(c[2]), "+f"(c[3])
        : "r"(a[0]), "r"(a[1]), "r"(a[2]), "r"(a[3]), "r"(b0), "r"(b1));
}
__device__ __forceinline__ void cp16(uint32_t dst, const void* src) {
    asm volatile("cp.async.cg.shared.global [%0], [%1], 16;" :: "r"(dst), "l"(src));
}
#define CP_COMMIT() asm volatile("cp.async.commit_group;" ::: "memory")
#define CP_WAIT1()  asm volatile("cp.async.wait_group 1;" ::: "memory")
#define CP_WAIT2()  asm volatile("cp.async.wait_group 2;" ::: "memory")

__device__ __forceinline__ uint32_t pkh(float a, float b) {   // a in low half
    __half2 x = __floats2half2_rn(a, b);
    return *reinterpret_cast<uint32_t*>(&x);
}
// 16B-chunk swizzle within 128B rows (conflict-free ldmatrix)
__device__ __forceinline__ uint32_t swz(int r, int c) {
    return (uint32_t)r * 128u + (uint32_t)((c ^ (r & 7)) & 7) * 16u;
}

// ---------------- fused convert kernel ---------------------------------------
// blocks [0, 4096): x cast, 4 elems/thread
// blocks [4096, 4864): W_qkv transpose-cast (48 x 16 tiles of 32x32)
// blocks [4864, 5120): W_out transpose-cast (16 x 16 tiles)
__global__ void __launch_bounds__(256, 8)
k_convert(const float* __restrict__ x, const float* __restrict__ Wq,
          const float* __restrict__ Wo,
          __half* __restrict__ xo, __half* __restrict__ wqo,
          __half* __restrict__ woo) {
    __shared__ float t[32][33];
    const int bid = blockIdx.x, tid = threadIdx.x;
    if (bid < 4096) {
        int i = bid * 1024 + tid * 4;
        float4 f = *reinterpret_cast<const float4*>(x + i);
        uint32_t p0 = pkh(f.x, f.y), p1 = pkh(f.z, f.w);
        *reinterpret_cast<uint2*>(xo + i) = make_uint2(p0, p1);
        return;
    }
    const int tx = tid & 31, ty = tid >> 5;   // 32 x 8
    const float* in;
    __half* o;
    int K, N, bn, bk;
    if (bid < 4096 + 768) {
        int j = bid - 4096;
        in = Wq; o = wqo; K = 512; N = 1536;
        bn = (j % 48) * 32; bk = (j / 48) * 32;
    } else {
        int j = bid - 4096 - 768;
        in = Wo; o = woo; K = 512; N = 512;
        bn = (j % 16) * 32; bk = (j / 16) * 32;
    }
#pragma unroll
    for (int j = 0; j < 32; j += 8)
        t[ty + j][tx] = in[(size_t)(bk + ty + j) * N + bn + tx];
    __syncthreads();
#pragma unroll
    for (int j = 0; j < 32; j += 8)
        o[(size_t)(bn + ty + j) * K + bk + tx] = __float2half_rn(t[tx][ty + j]);
}

// ---------------- fp16 GEMM, 256 threads, 2 CTAs/SM, 3-stage ring ------------
// tile 128x128, warp grid 4x2, warp tile 32x64, k-chunk 64, 3x32KB stages.
// MODE 0: -> q/k/v fp16 per-head layout (q pre-scaled);  MODE 1: fp32 + bias.
template <int MODE>
__global__ void __launch_bounds__(256, 2)
gemm_mma(const __half* __restrict__ Ah, const __half* __restrict__ Bh, int Kd,
         __half* __restrict__ q, __half* __restrict__ k, __half* __restrict__ v,
         const float* __restrict__ log_temp,
         const float* __restrict__ bias, float* __restrict__ outp) {
    extern __shared__ char smc[];
    const uint32_t sb = smem_u32(smc);
    const int tid = threadIdx.x, w = tid >> 5, lane = tid & 31;
    const int m0 = blockIdx.y * 128, n0 = blockIdx.x * 128;
    const int wm = w & 3, wn = w >> 2;
    const uint32_t STG = 32768;   // A 16K | B 16K

    float acc[2][8][4] = {};

    auto issue = [&](int kc, int stg) {
        uint32_t base = sb + (uint32_t)stg * STG;
#pragma unroll
        for (int i = tid; i < 1024; i += 256) {
            int r = i >> 3, c = i & 7;
            uint32_t off = swz(r, c);
            cp16(base + off,         Ah + (size_t)(m0 + r) * Kd + kc + c * 8);
            cp16(base + 16384 + off, Bh + (size_t)(n0 + r) * Kd + kc + c * 8);
        }
    };

    const int nch = Kd / 64;   // 8
    issue(0, 0); CP_COMMIT();
    issue(64, 1); CP_COMMIT();

    int stg = 0, nstg = 2;   // stage of kc; stage to fill next
    for (int kc = 0; kc < nch; kc++) {
        if (kc + 2 < nch) issue((kc + 2) * 64, nstg);
        CP_COMMIT();
        CP_WAIT2();
        __syncthreads();

        const uint32_t As = sb + (uint32_t)stg * STG;
        const uint32_t Bs = As + 16384;
#pragma unroll
        for (int ks = 0; ks < 4; ks++) {
            uint32_t ah[2][4];
#pragma unroll
            for (int mt = 0; mt < 2; mt++) {
                int rr = 32 * wm + 16 * mt + (lane & 7) + ((lane >> 3) & 1) * 8;
                int cc = 2 * ks + (lane >> 4);
                ldsm4(ah[mt][0], ah[mt][1], ah[mt][2], ah[mt][3], As + swz(rr, cc));
            }
#pragma unroll
            for (int nb = 0; nb < 4; nb++) {
                int rr = 64 * wn + 16 * nb + (lane & 7) + ((lane >> 4) ? 8 : 0);
                int cc = 2 * ks + ((lane >> 3) & 1);
                uint32_t b0, b1, b2, b3;
                ldsm4(b0, b1, b2, b3, Bs + swz(rr, cc));
#pragma unroll
                for (int mt = 0; mt < 2; mt++) {
                    mma_f16(acc[mt][2 * nb],     ah[mt], b0, b1);
                    mma_f16(acc[mt][2 * nb + 1], ah[mt], b2, b3);
                }
            }
        }
        __syncthreads();
        stg = (stg + 1 == 3) ? 0 : stg + 1;
        nstg = (nstg + 1 == 3) ? 0 : nstg + 1;
    }

    // epilogue
    const float qscale = (MODE == 0) ? __expf(*log_temp) * 1.4426950408889634f : 1.f;
#pragma unroll
    for (int mt = 0; mt < 2; mt++) {
#pragma unroll
        for (int i = 0; i < 2; i++) {
            const int gm = m0 + 32 * wm + 16 * mt + (lane >> 2) + i * 8;
#pragma unroll
            for (int nt = 0; nt < 8; nt++) {
                const int gn = n0 + 64 * wn + 8 * nt + 2 * (lane & 3);
                float v0 = acc[mt][nt][2 * i], v1 = acc[mt][nt][2 * i + 1];
                if (MODE == 0) {
                    const int seg = gn >> 9, nn = gn & 511;
                    const int h = nn >> 6, d = nn & 63;
                    const int bI = gm >> 11, s = gm & 2047;
                    size_t idx = ((size_t)((bI * 8 + h) * 2048 + s)) * 64 + d;
                    if (seg == 0) { v0 *= qscale; v1 *= qscale; }
                    __half* dst = (seg == 0) ? q : (seg == 1) ? k : v;
                    *reinterpret_cast<uint32_t*>(dst + idx) = pkh(v0, v1);
                } else {
                    float2 o = make_float2(v0 + bias[gn], v1 + bias[gn + 1]);
                    *reinterpret_cast<float2*>(outp + (size_t)gm * 512 + gn) = o;
                }
            }
        }
    }
}

// ---------------- attention: fp16 HMMA flash (scale pre-folded into q) -------
__global__ void __launch_bounds__(256, 2)
attn_mma(const __half* __restrict__ qg, const __half* __restrict__ kg,
         const __half* __restrict__ vg, __half* __restrict__ aout) {
    extern __shared__ char smc[];
    const uint32_t sb = smem_u32(smc);
    const int tid = threadIdx.x, w = tid >> 5, lane = tid & 31;
    const int q0 = blockIdx.x * 128;
    const int bh = blockIdx.y, b = bh >> 3, h = bh & 7;
    const uint32_t KO = 0, VO = 16384, STG = 32768, QO = 65536;

    const size_t bho = (size_t)bh * 2048 * 64;

    // Q -> smem
#pragma unroll
    for (int i = tid; i < 1024; i += 256) {
        int r = i >> 3, c = i & 7;
        *reinterpret_cast<uint4*>(smc + QO + swz(r, c)) =
            *reinterpret_cast<const uint4*>(qg + bho + (size_t)(q0 + r) * 64 + c * 8);
    }

    auto issue = [&](int t, int stg) {
        const size_t o = bho + (size_t)t * 128 * 64;
        uint32_t base = sb + (uint32_t)stg * STG;
#pragma unroll
        for (int i = tid; i < 1024; i += 256) {
            int r = i >> 3, c = i & 7;
            uint32_t off = swz(r, c);
            size_t g = o + (size_t)r * 64 + c * 8;
            cp16(base + KO + off, kg + g);
            cp16(base + VO + off, vg + g);
        }
    };
    issue(0, 0); CP_COMMIT();
    __syncthreads();   // Q visible

    uint32_t aq[4][4];
    {
        int rr = 16 * w + (lane & 7) + ((lane >> 3) & 1) * 8;
#pragma unroll
        for (int ks = 0; ks < 4; ks++) {
            int cc = 2 * ks + (lane >> 4);
            ldsm4(aq[ks][0], aq[ks][1], aq[ks][2], aq[ks][3], sb + QO + swz(rr, cc));
        }
    }

    float O[8][4] = {};
    float l0 = 0.f, l1 = 0.f;
    const int rg = 16 * w + (lane >> 2);
    const int qi0 = q0 + rg, qi1 = qi0 + 8;

    for (int t = 0; t < 16; t++) {
        if (t + 1 < 16) issue(t + 1, (t + 1) & 1);
        CP_COMMIT();
        CP_WAIT1();
        __syncthreads();

        const uint32_t stgb = sb + (uint32_t)(t & 1) * STG;
        const uint32_t Ks = stgb + KO, Vs = stgb + VO;

        uint32_t ep[16][2];
#pragma unroll
        for (int half = 0; half < 2; half++) {
            float S[8][4] = {};
#pragma unroll
            for (int ks = 0; ks < 4; ks++) {
#pragma unroll
                for (int ntp = 0; ntp < 4; ntp++) {
                    uint32_t b0, b1, b2, b3;
                    int rr = 16 * (4 * half + ntp) + (lane & 7) + ((lane >> 4) ? 8 : 0);
                    int cc = 2 * ks + ((lane >> 3) & 1);
                    ldsm4(b0, b1, b2, b3, Ks + swz(rr, cc));
                    mma_f16(S[2 * ntp],     aq[ks], b0, b1);
                    mma_f16(S[2 * ntp + 1], aq[ks], b2, b3);
                }
            }
#pragma unroll
            for (int s = 0; s < 8; s++) {
                int nt = 8 * half + s;
                int jc = t * 128 + 8 * nt + 2 * (lane & 3);
                float e0 = (jc     == qi0) ? 0.f : exp2f(S[s][0]);
                float e1 = (jc + 1 == qi0) ? 0.f : exp2f(S[s][1]);
                float e2 = (jc     == qi1) ? 0.f : exp2f(S[s][2]);
                float e3 = (jc + 1 == qi1) ? 0.f : exp2f(S[s][3]);
                l0 += e0 + e1;
                l1 += e2 + e3;
                ep[nt][0] = pkh(e0, e1);
                ep[nt][1] = pkh(e2, e3);
            }
        }

        // O += P @ V
#pragma unroll
        for (int ks = 0; ks < 8; ks++) {
            uint32_t ap[4] = { ep[2 * ks][0], ep[2 * ks][1],
                               ep[2 * ks + 1][0], ep[2 * ks + 1][1] };
#pragma unroll
            for (int ntp = 0; ntp < 4; ntp++) {
                uint32_t b0, b1, b2, b3;
                int rr = 16 * ks + (lane & 7) + ((lane >> 3) & 1) * 8;
                int cc = 2 * ntp + (lane >> 4);
                ldsm4t(b0, b1, b2, b3, Vs + swz(rr, cc));
                mma_f16(O[2 * ntp],     ap, b0, b1);
                mma_f16(O[2 * ntp + 1], ap, b2, b3);
            }
        }
        __syncthreads();
    }

    l0 += __shfl_xor_sync(0xffffffffu, l0, 1);
    l0 += __shfl_xor_sync(0xffffffffu, l0, 2);
    l1 += __shfl_xor_sync(0xffffffffu, l1, 1);
    l1 += __shfl_xor_sync(0xffffffffu, l1, 2);
    const float inv0 = 1.f / l0, inv1 = 1.f / l1;

#pragma unroll
    for (int i = 0; i < 2; i++) {
        const float inv = i ? inv1 : inv0;
        const size_t gm = (size_t)(b * 2048 + q0 + rg + i * 8);
#pragma unroll
        for (int nt = 0; nt < 8; nt++) {
            const int d = 8 * nt + 2 * (lane & 3);
            size_t idx = gm * INNER + h * DHEAD + d;
            *reinterpret_cast<uint32_t*>(aout + idx) =
                pkh(O[nt][2 * i] * inv, O[nt][2 * i + 1] * inv);
        }
    }
}

// ---------------- launch -----------------------------------------------------
extern "C" void kernel_launch(void* const* d_in, const int* in_sizes, int n_in,
                              void* d_out, int out_size) {
    const float* x        = (const float*)d_in[0];
    const float* W_qkv    = (const float*)d_in[1];
    const float* log_temp = (const float*)d_in[2];
    const float* W_out    = (const float*)d_in[3];
    const float* b_out    = (const float*)d_in[4];
    float* out = (float*)d_out;

    __half *xh, *wq, *wo, *q, *k, *v, *a;
    cudaGetSymbolAddress((void**)&xh, g_x);
    cudaGetSymbolAddress((void**)&wq, g_wq);
    cudaGetSymbolAddress((void**)&wo, g_wo);
    cudaGetSymbolAddress((void**)&q, g_q);
    cudaGetSymbolAddress((void**)&k, g_k);
    cudaGetSymbolAddress((void**)&v, g_v);
    cudaGetSymbolAddress((void**)&a, g_a);

    const int GSM = 98304;   // 3 stages x 32KB
    const int ASM = 81920;   // 2 stages x 32KB + Q 16KB
    cudaFuncSetAttribute(gemm_mma<0>, cudaFuncAttributeMaxDynamicSharedMemorySize, GSM);
    cudaFuncSetAttribute(gemm_mma<1>, cudaFuncAttributeMaxDynamicSharedMemorySize, GSM);
    cudaFuncSetAttribute(attn_mma,    cudaFuncAttributeMaxDynamicSharedMemorySize, ASM);

    // fused converts (x cast + both weight transposes), one launch
    k_convert<<<5120, 256>>>(x, W_qkv, W_out, xh, wq, wo);

    // 1) QKV projection (q pre-scaled by exp(log_temp)*log2e)
    gemm_mma<0><<<dim3(12, 64), 256, GSM>>>(xh, wq, DIMX, q, k, v,
                                            log_temp, nullptr, nullptr);
    // 2) attention
    attn_mma<<<dim3(SSEQ / 128, BB * HEADS), 256, ASM>>>(q, k, v, a);
    // 3) output projection + bias -> fp32
    gemm_mma<1><<<dim3(4, 64), 256, GSM>>>(a, wo, INNER, nullptr, nullptr, nullptr,
                                           nullptr, b_out, out);
}

// round 14
// speedup vs baseline: 1.5448x; 1.0332x over previous
#include <cuda_runtime.h>
#include <cuda_fp16.h>
#include <cstdint>
#include <math.h>

#define BB 4
#define SSEQ 2048
#define DIMX 512
#define HEADS 8
#define DHEAD 64
#define INNER 512
#define NROWS (BB * SSEQ)   // 8192
#define NX  (NROWS * DIMX)  // 4194304

// ---------------- device scratch -------------------------------------------
__device__ __half g_x[NX];
__device__ __half g_wq[3 * INNER * DIMX];   // W_qkv^T [1536][512]
__device__ __half g_wo[DIMX * INNER];       // W_out^T [512][512]
__device__ __half g_q[NROWS * INNER];       // [bh][s][64], pre-scaled
__device__ __half g_k[NROWS * INNER];
__device__ __half g_v[NROWS * INNER];
__device__ __half g_a[NROWS * INNER];       // [b*s][512]

// ---------------- helpers ---------------------------------------------------
__device__ __forceinline__ uint32_t smem_u32(const void* p) {
    uint32_t a;
    asm("{ .reg .u64 t; cvta.to.shared.u64 t, %1; cvt.u32.u64 %0, t; }" : "=r"(a) : "l"(p));
    return a;
}
__device__ __forceinline__ void ldsm4(uint32_t& r0, uint32_t& r1, uint32_t& r2,
                                      uint32_t& r3, uint32_t addr) {
    asm volatile("ldmatrix.sync.aligned.m8n8.x4.shared.b16 {%0,%1,%2,%3}, [%4];"
                 : "=r"(r0), "=r"(r1), "=r"(r2), "=r"(r3) : "r"(addr));
}
__device__ __forceinline__ void ldsm4t(uint32_t& r0, uint32_t& r1, uint32_t& r2,
                                       uint32_t& r3, uint32_t addr) {
    asm volatile("ldmatrix.sync.aligned.m8n8.x4.trans.shared.b16 {%0,%1,%2,%3}, [%4];"
                 : "=r"(r0), "=r"(r1), "=r"(r2), "=r"(r3) : "r"(addr));
}
__device__ __forceinline__ void mma_f16(float* c, const uint32_t a[4],
                                        uint32_t b0, uint32_t b1) {
    asm volatile(
        "mma.sync.aligned.m16n8k16.row.col.f32.f16.f16.f32 "
        "{%0,%1,%2,%3}, {%4,%5,%6,%7}, {%8,%9}, {%0,%1,%2,%3};"
        : "+f"(c[0]), "+f"(c[1]), "+f"(c[2]), "+f"(c[3])
        : "r"(a[0]), "r"(a[1]), "r"(a[2]), "r"(a[3]), "r"(b0), "r"(b1));
}
__device__ __forceinline__ void cp16(uint32_t dst, const void* src) {
    asm volatile("cp.async.cg.shared.global [%0], [%1], 16;" :: "r"(dst), "l"(src));
}
#define CP_COMMIT() asm volatile("cp.async.commit_group;" ::: "memory")
#define CP_WAIT1()  asm volatile("cp.async.wait_group 1;" ::: "memory")
#define CP_WAIT2()  asm volatile("cp.async.wait_group 2;" ::: "memory")

__device__ __forceinline__ uint32_t pkh(float a, float b) {   // a in low half
    __half2 x = __floats2half2_rn(a, b);
    return *reinterpret_cast<uint32_t*>(&x);
}
// 16B-chunk swizzle within 128B rows (conflict-free ldmatrix)
__device__ __forceinline__ uint32_t swz(int r, int c) {
    return (uint32_t)r * 128u + (uint32_t)((c ^ (r & 7)) & 7) * 16u;
}

// ---------------- fused convert kernel (unchanged) ---------------------------
__global__ void __launch_bounds__(256, 8)
k_convert(const float* __restrict__ x, const float* __restrict__ Wq,
          const float* __restrict__ Wo,
          __half* __restrict__ xo, __half* __restrict__ wqo,
          __half* __restrict__ woo) {
    __shared__ float t[32][33];
    const int bid = blockIdx.x, tid = threadIdx.x;
    if (bid < 4096) {
        int i = bid * 1024 + tid * 4;
        float4 f = *reinterpret_cast<const float4*>(x + i);
        uint32_t p0 = pkh(f.x, f.y), p1 = pkh(f.z, f.w);
        *reinterpret_cast<uint2*>(xo + i) = make_uint2(p0, p1);
        return;
    }
    const int tx = tid & 31, ty = tid >> 5;   // 32 x 8
    const float* in;
    __half* o;
    int K, N, bn, bk;
    if (bid < 4096 + 768) {
        int j = bid - 4096;
        in = Wq; o = wqo; K = 512; N = 1536;
        bn = (j % 48) * 32; bk = (j / 48) * 32;
    } else {
        int j = bid - 4096 - 768;
        in = Wo; o = woo; K = 512; N = 512;
        bn = (j % 16) * 32; bk = (j / 16) * 32;
    }
#pragma unroll
    for (int j = 0; j < 32; j += 8)
        t[ty + j][tx] = in[(size_t)(bk + ty + j) * N + bn + tx];
    __syncthreads();
#pragma unroll
    for (int j = 0; j < 32; j += 8)
        o[(size_t)(bn + ty + j) * K + bk + tx] = __float2half_rn(t[tx][ty + j]);
}

// ---------------- fp16 GEMM (unchanged from R13) -----------------------------
template <int MODE>
__global__ void __launch_bounds__(256, 2)
gemm_mma(const __half* __restrict__ Ah, const __half* __restrict__ Bh, int Kd,
         __half* __restrict__ q, __half* __restrict__ k, __half* __restrict__ v,
         const float* __restrict__ log_temp,
         const float* __restrict__ bias, float* __restrict__ outp) {
    extern __shared__ char smc[];
    const uint32_t sb = smem_u32(smc);
    const int tid = threadIdx.x, w = tid >> 5, lane = tid & 31;
    const int m0 = blockIdx.y * 128, n0 = blockIdx.x * 128;
    const int wm = w & 3, wn = w >> 2;
    const uint32_t STG = 32768;

    float acc[2][8][4] = {};

    auto issue = [&](int kc, int stg) {
        uint32_t base = sb + (uint32_t)stg * STG;
#pragma unroll
        for (int i = tid; i < 1024; i += 256) {
            int r = i >> 3, c = i & 7;
            uint32_t off = swz(r, c);
            cp16(base + off,         Ah + (size_t)(m0 + r) * Kd + kc + c * 8);
            cp16(base + 16384 + off, Bh + (size_t)(n0 + r) * Kd + kc + c * 8);
        }
    };

    const int nch = Kd / 64;
    issue(0, 0); CP_COMMIT();
    issue(64, 1); CP_COMMIT();

    int stg = 0, nstg = 2;
    for (int kc = 0; kc < nch; kc++) {
        if (kc + 2 < nch) issue((kc + 2) * 64, nstg);
        CP_COMMIT();
        CP_WAIT2();
        __syncthreads();

        const uint32_t As = sb + (uint32_t)stg * STG;
        const uint32_t Bs = As + 16384;
#pragma unroll
        for (int ks = 0; ks < 4; ks++) {
            uint32_t ah[2][4];
#pragma unroll
            for (int mt = 0; mt < 2; mt++) {
                int rr = 32 * wm + 16 * mt + (lane & 7) + ((lane >> 3) & 1) * 8;
                int cc = 2 * ks + (lane >> 4);
                ldsm4(ah[mt][0], ah[mt][1], ah[mt][2], ah[mt][3], As + swz(rr, cc));
            }
#pragma unroll
            for (int nb = 0; nb < 4; nb++) {
                int rr = 64 * wn + 16 * nb + (lane & 7) + ((lane >> 4) ? 8 : 0);
                int cc = 2 * ks + ((lane >> 3) & 1);
                uint32_t b0, b1, b2, b3;
                ldsm4(b0, b1, b2, b3, Bs + swz(rr, cc));
#pragma unroll
                for (int mt = 0; mt < 2; mt++) {
                    mma_f16(acc[mt][2 * nb],     ah[mt], b0, b1);
                    mma_f16(acc[mt][2 * nb + 1], ah[mt], b2, b3);
                }
            }
        }
        __syncthreads();
        stg = (stg + 1 == 3) ? 0 : stg + 1;
        nstg = (nstg + 1 == 3) ? 0 : nstg + 1;
    }

    const float qscale = (MODE == 0) ? __expf(*log_temp) * 1.4426950408889634f : 1.f;
#pragma unroll
    for (int mt = 0; mt < 2; mt++) {
#pragma unroll
        for (int i = 0; i < 2; i++) {
            const int gm = m0 + 32 * wm + 16 * mt + (lane >> 2) + i * 8;
#pragma unroll
            for (int nt = 0; nt < 8; nt++) {
                const int gn = n0 + 64 * wn + 8 * nt + 2 * (lane & 3);
                float v0 = acc[mt][nt][2 * i], v1 = acc[mt][nt][2 * i + 1];
                if (MODE == 0) {
                    const int seg = gn >> 9, nn = gn & 511;
                    const int h = nn >> 6, d = nn & 63;
                    const int bI = gm >> 11, s = gm & 2047;
                    size_t idx = ((size_t)((bI * 8 + h) * 2048 + s)) * 64 + d;
                    if (seg == 0) { v0 *= qscale; v1 *= qscale; }
                    __half* dst = (seg == 0) ? q : (seg == 1) ? k : v;
                    *reinterpret_cast<uint32_t*>(dst + idx) = pkh(v0, v1);
                } else {
                    float2 o = make_float2(v0 + bias[gn], v1 + bias[gn + 1]);
                    *reinterpret_cast<float2*>(outp + (size_t)gm * 512 + gn) = o;
                }
            }
        }
    }
}

// ---------------- attention v2: q-tile 256, warp m-tile 32 -------------------
// Each warp owns 32 q-rows (2 x m16); K/V fragments loaded once, reused for
// both m16 tiles -> smem reads per FMA halved. PV done per 64-col half.
__global__ void __launch_bounds__(256, 1)
attn_mma(const __half* __restrict__ qg, const __half* __restrict__ kg,
         const __half* __restrict__ vg, __half* __restrict__ aout) {
    extern __shared__ char smc[];
    const uint32_t sb = smem_u32(smc);
    const int tid = threadIdx.x, w = tid >> 5, lane = tid & 31;
    const int q0 = blockIdx.x * 256;
    const int bh = blockIdx.y, b = bh >> 3, h = bh & 7;
    const uint32_t KO = 0, VO = 16384, STG = 32768, QO = 65536;

    const size_t bho = (size_t)bh * 2048 * 64;

    // Q tile (256 x 64) -> smem
#pragma unroll
    for (int i = tid; i < 2048; i += 256) {
        int r = i >> 3, c = i & 7;
        *reinterpret_cast<uint4*>(smc + QO + swz(r, c)) =
            *reinterpret_cast<const uint4*>(qg + bho + (size_t)(q0 + r) * 64 + c * 8);
    }

    auto issue = [&](int t, int stg) {
        const size_t o = bho + (size_t)t * 128 * 64;
        uint32_t base = sb + (uint32_t)stg * STG;
#pragma unroll
        for (int i = tid; i < 1024; i += 256) {
            int r = i >> 3, c = i & 7;
            uint32_t off = swz(r, c);
            size_t g = o + (size_t)r * 64 + c * 8;
            cp16(base + KO + off, kg + g);
            cp16(base + VO + off, vg + g);
        }
    };
    issue(0, 0); CP_COMMIT();
    __syncthreads();   // Q visible

    // Q fragments for both m16 tiles (persist)
    uint32_t aq[2][4][4];
#pragma unroll
    for (int mt = 0; mt < 2; mt++) {
        int rr = 32 * w + 16 * mt + (lane & 7) + ((lane >> 3) & 1) * 8;
#pragma unroll
        for (int ks = 0; ks < 4; ks++) {
            int cc = 2 * ks + (lane >> 4);
            ldsm4(aq[mt][ks][0], aq[mt][ks][1], aq[mt][ks][2], aq[mt][ks][3],
                  sb + QO + swz(rr, cc));
        }
    }

    float O[2][8][4] = {};
    float l[2][2] = {};
    const int rbase = q0 + 32 * w + (lane >> 2);   // mt adds 16*mt, i adds 8*i

    for (int t = 0; t < 16; t++) {
        if (t + 1 < 16) issue(t + 1, (t + 1) & 1);
        CP_COMMIT();
        CP_WAIT1();
        __syncthreads();

        const uint32_t stgb = sb + (uint32_t)(t & 1) * STG;
        const uint32_t Ks = stgb + KO, Vs = stgb + VO;

#pragma unroll
        for (int half = 0; half < 2; half++) {
            // S for both m16 tiles over 64 KV cols; B loaded once per fragment
            float S[2][8][4] = {};
#pragma unroll
            for (int ks = 0; ks < 4; ks++) {
#pragma unroll
                for (int ntp = 0; ntp < 4; ntp++) {
                    uint32_t b0, b1, b2, b3;
                    int rr = 16 * (4 * half + ntp) + (lane & 7) + ((lane >> 4) ? 8 : 0);
                    int cc = 2 * ks + ((lane >> 3) & 1);
                    ldsm4(b0, b1, b2, b3, Ks + swz(rr, cc));
#pragma unroll
                    for (int mt = 0; mt < 2; mt++) {
                        mma_f16(S[mt][2 * ntp],     aq[mt][ks], b0, b1);
                        mma_f16(S[mt][2 * ntp + 1], aq[mt][ks], b2, b3);
                    }
                }
            }

            // exp + diag mask -> fp16 P fragments
            uint32_t ep[2][8][2];
#pragma unroll
            for (int mt = 0; mt < 2; mt++) {
                const int qi0 = rbase + 16 * mt, qi1 = qi0 + 8;
#pragma unroll
                for (int s = 0; s < 8; s++) {
                    int jc = t * 128 + 64 * half + 8 * s + 2 * (lane & 3);
                    float e0 = (jc     == qi0) ? 0.f : exp2f(S[mt][s][0]);
                    float e1 = (jc + 1 == qi0) ? 0.f : exp2f(S[mt][s][1]);
                    float e2 = (jc     == qi1) ? 0.f : exp2f(S[mt][s][2]);
                    float e3 = (jc + 1 == qi1) ? 0.f : exp2f(S[mt][s][3]);
                    l[mt][0] += e0 + e1;
                    l[mt][1] += e2 + e3;
                    ep[mt][s][0] = pkh(e0, e1);
                    ep[mt][s][1] = pkh(e2, e3);
                }
            }

            // O += P @ V over this half's 64 KV rows; V loaded once per fragment
#pragma unroll
            for (int ks2 = 0; ks2 < 4; ks2++) {
#pragma unroll
                for (int ntp = 0; ntp < 4; ntp++) {
                    uint32_t b0, b1, b2, b3;
                    int rr = 16 * (4 * half + ks2) + (lane & 7) + ((lane >> 3) & 1) * 8;
                    int cc = 2 * ntp + (lane >> 4);
                    ldsm4t(b0, b1, b2, b3, Vs + swz(rr, cc));
#pragma unroll
                    for (int mt = 0; mt < 2; mt++) {
                        uint32_t ap[4] = { ep[mt][2 * ks2][0], ep[mt][2 * ks2][1],
                                           ep[mt][2 * ks2 + 1][0], ep[mt][2 * ks2 + 1][1] };
                        mma_f16(O[mt][2 * ntp],     ap, b0, b1);
                        mma_f16(O[mt][2 * ntp + 1], ap, b2, b3);
                    }
                }
            }
        }
        __syncthreads();
    }

#pragma unroll
    for (int mt = 0; mt < 2; mt++) {
#pragma unroll
        for (int i = 0; i < 2; i++) {
            float li = l[mt][i];
            li += __shfl_xor_sync(0xffffffffu, li, 1);
            li += __shfl_xor_sync(0xffffffffu, li, 2);
            const float inv = 1.f / li;
            const size_t gm = (size_t)(b * 2048 + rbase + 16 * mt + 8 * i);
#pragma unroll
            for (int nt = 0; nt < 8; nt++) {
                const int d = 8 * nt + 2 * (lane & 3);
                size_t idx = gm * INNER + h * DHEAD + d;
                *reinterpret_cast<uint32_t*>(aout + idx) =
                    pkh(O[mt][nt][2 * i] * inv, O[mt][nt][2 * i + 1] * inv);
            }
        }
    }
}

// ---------------- launch -----------------------------------------------------
extern "C" void kernel_launch(void* const* d_in, const int* in_sizes, int n_in,
                              void* d_out, int out_size) {
    const float* x        = (const float*)d_in[0];
    const float* W_qkv    = (const float*)d_in[1];
    const float* log_temp = (const float*)d_in[2];
    const float* W_out    = (const float*)d_in[3];
    const float* b_out    = (const float*)d_in[4];
    float* out = (float*)d_out;

    __half *xh, *wq, *wo, *q, *k, *v, *a;
    cudaGetSymbolAddress((void**)&xh, g_x);
    cudaGetSymbolAddress((void**)&wq, g_wq);
    cudaGetSymbolAddress((void**)&wo, g_wo);
    cudaGetSymbolAddress((void**)&q, g_q);
    cudaGetSymbolAddress((void**)&k, g_k);
    cudaGetSymbolAddress((void**)&v, g_v);
    cudaGetSymbolAddress((void**)&a, g_a);

    const int GSM = 98304;   // 3 stages x 32KB
    const int ASM = 98304;   // 2 KV stages x 32KB + Q 32KB
    cudaFuncSetAttribute(gemm_mma<0>, cudaFuncAttributeMaxDynamicSharedMemorySize, GSM);
    cudaFuncSetAttribute(gemm_mma<1>, cudaFuncAttributeMaxDynamicSharedMemorySize, GSM);
    cudaFuncSetAttribute(attn_mma,    cudaFuncAttributeMaxDynamicSharedMemorySize, ASM);

    k_convert<<<5120, 256>>>(x, W_qkv, W_out, xh, wq, wo);

    // 1) QKV projection (q pre-scaled by exp(log_temp)*log2e)
    gemm_mma<0><<<dim3(12, 64), 256, GSM>>>(xh, wq, DIMX, q, k, v,
                                            log_temp, nullptr, nullptr);
    // 2) attention (q-tile 256, warp m-tile 32)
    attn_mma<<<dim3(SSEQ / 256, BB * HEADS), 256, ASM>>>(q, k, v, a);
    // 3) output projection + bias -> fp32
    gemm_mma<1><<<dim3(4, 64), 256, GSM>>>(a, wo, INNER, nullptr, nullptr, nullptr,
                                           nullptr, b_out, out);
}

// round 15
// speedup vs baseline: 1.5484x; 1.0024x over previous
#include <cuda_runtime.h>
#include <cuda_fp16.h>
#include <cstdint>
#include <math.h>

#define BB 4
#define SSEQ 2048
#define DIMX 512
#define HEADS 8
#define DHEAD 64
#define INNER 512
#define NROWS (BB * SSEQ)   // 8192
#define NX  (NROWS * DIMX)  // 4194304

// ---------------- device scratch -------------------------------------------
__device__ __half g_x[NX];
__device__ __half g_wq[3 * INNER * DIMX];   // W_qkv^T [1536][512]
__device__ __half g_wo[DIMX * INNER];       // W_out^T [512][512]
__device__ __half g_q[NROWS * INNER];       // [bh][s][64], pre-scaled
__device__ __half g_k[NROWS * INNER];
__device__ __half g_v[NROWS * INNER];
__device__ __half g_a[NROWS * INNER];       // [b*s][512]

// ---------------- helpers ---------------------------------------------------
__device__ __forceinline__ uint32_t smem_u32(const void* p) {
    uint32_t a;
    asm("{ .reg .u64 t; cvta.to.shared.u64 t, %1; cvt.u32.u64 %0, t; }" : "=r"(a) : "l"(p));
    return a;
}
__device__ __forceinline__ void ldsm4(uint32_t& r0, uint32_t& r1, uint32_t& r2,
                                      uint32_t& r3, uint32_t addr) {
    asm volatile("ldmatrix.sync.aligned.m8n8.x4.shared.b16 {%0,%1,%2,%3}, [%4];"
                 : "=r"(r0), "=r"(r1), "=r"(r2), "=r"(r3) : "r"(addr));
}
__device__ __forceinline__ void ldsm4t(uint32_t& r0, uint32_t& r1, uint32_t& r2,
                                       uint32_t& r3, uint32_t addr) {
    asm volatile("ldmatrix.sync.aligned.m8n8.x4.trans.shared.b16 {%0,%1,%2,%3}, [%4];"
                 : "=r"(r0), "=r"(r1), "=r"(r2), "=r"(r3) : "r"(addr));
}
__device__ __forceinline__ void mma_f16(float* c, const uint32_t a[4],
                                        uint32_t b0, uint32_t b1) {
    asm volatile(
        "mma.sync.aligned.m16n8k16.row.col.f32.f16.f16.f32 "
        "{%0,%1,%2,%3}, {%4,%5,%6,%7}, {%8,%9}, {%0,%1,%2,%3};"
        : "+f"(c[0]), "+f"(c[1]), "+f"(c[2]), "+f"(c[3])
        : "r"(a[0]), "r"(a[1]), "r"(a[2]), "r"(a[3]), "r"(b0), "r"(b1));
}
__device__ __forceinline__ void cp16(uint32_t dst, const void* src) {
    asm volatile("cp.async.cg.shared.global [%0], [%1], 16;" :: "r"(dst), "l"(src));
}
#define CP_COMMIT() asm volatile("cp.async.commit_group;" ::: "memory")
#define CP_WAIT1()  asm volatile("cp.async.wait_group 1;" ::: "memory")
#define CP_WAIT2()  asm volatile("cp.async.wait_group 2;" ::: "memory")

__device__ __forceinline__ uint32_t pkh(float a, float b) {   // a in low half
    __half2 x = __floats2half2_rn(a, b);
    return *reinterpret_cast<uint32_t*>(&x);
}
// 16B-chunk swizzle within 128B rows (conflict-free ldmatrix)
__device__ __forceinline__ uint32_t swz(int r, int c) {
    return (uint32_t)r * 128u + (uint32_t)((c ^ (r & 7)) & 7) * 16u;
}

// ---------------- fused convert kernel (unchanged) ---------------------------
__global__ void __launch_bounds__(256, 8)
k_convert(const float* __restrict__ x, const float* __restrict__ Wq,
          const float* __restrict__ Wo,
          __half* __restrict__ xo, __half* __restrict__ wqo,
          __half* __restrict__ woo) {
    __shared__ float t[32][33];
    const int bid = blockIdx.x, tid = threadIdx.x;
    if (bid < 4096) {
        int i = bid * 1024 + tid * 4;
        float4 f = *reinterpret_cast<const float4*>(x + i);
        uint32_t p0 = pkh(f.x, f.y), p1 = pkh(f.z, f.w);
        *reinterpret_cast<uint2*>(xo + i) = make_uint2(p0, p1);
        return;
    }
    const int tx = tid & 31, ty = tid >> 5;   // 32 x 8
    const float* in;
    __half* o;
    int K, N, bn, bk;
    if (bid < 4096 + 768) {
        int j = bid - 4096;
        in = Wq; o = wqo; K = 512; N = 1536;
        bn = (j % 48) * 32; bk = (j / 48) * 32;
    } else {
        int j = bid - 4096 - 768;
        in = Wo; o = woo; K = 512; N = 512;
        bn = (j % 16) * 32; bk = (j / 16) * 32;
    }
#pragma unroll
    for (int j = 0; j < 32; j += 8)
        t[ty + j][tx] = in[(size_t)(bk + ty + j) * N + bn + tx];
    __syncthreads();
#pragma unroll
    for (int j = 0; j < 32; j += 8)
        o[(size_t)(bn + ty + j) * K + bk + tx] = __float2half_rn(t[tx][ty + j]);
}

// ---------------- fp16 GEMM (R13 shape; bias via float2) ---------------------
template <int MODE>
__global__ void __launch_bounds__(256, 2)
gemm_mma(const __half* __restrict__ Ah, const __half* __restrict__ Bh, int Kd,
         __half* __restrict__ q, __half* __restrict__ k, __half* __restrict__ v,
         const float* __restrict__ log_temp,
         const float* __restrict__ bias, float* __restrict__ outp) {
    extern __shared__ char smc[];
    const uint32_t sb = smem_u32(smc);
    const int tid = threadIdx.x, w = tid >> 5, lane = tid & 31;
    const int m0 = blockIdx.y * 128, n0 = blockIdx.x * 128;
    const int wm = w & 3, wn = w >> 2;
    const uint32_t STG = 32768;

    float acc[2][8][4] = {};

    auto issue = [&](int kc, int stg) {
        uint32_t base = sb + (uint32_t)stg * STG;
#pragma unroll
        for (int i = tid; i < 1024; i += 256) {
            int r = i >> 3, c = i & 7;
            uint32_t off = swz(r, c);
            cp16(base + off,         Ah + (size_t)(m0 + r) * Kd + kc + c * 8);
            cp16(base + 16384 + off, Bh + (size_t)(n0 + r) * Kd + kc + c * 8);
        }
    };

    const int nch = Kd / 64;
    issue(0, 0); CP_COMMIT();
    issue(64, 1); CP_COMMIT();

    int stg = 0, nstg = 2;
    for (int kc = 0; kc < nch; kc++) {
        if (kc + 2 < nch) issue((kc + 2) * 64, nstg);
        CP_COMMIT();
        CP_WAIT2();
        __syncthreads();

        const uint32_t As = sb + (uint32_t)stg * STG;
        const uint32_t Bs = As + 16384;
#pragma unroll
        for (int ks = 0; ks < 4; ks++) {
            uint32_t ah[2][4];
#pragma unroll
            for (int mt = 0; mt < 2; mt++) {
                int rr = 32 * wm + 16 * mt + (lane & 7) + ((lane >> 3) & 1) * 8;
                int cc = 2 * ks + (lane >> 4);
                ldsm4(ah[mt][0], ah[mt][1], ah[mt][2], ah[mt][3], As + swz(rr, cc));
            }
#pragma unroll
            for (int nb = 0; nb < 4; nb++) {
                int rr = 64 * wn + 16 * nb + (lane & 7) + ((lane >> 4) ? 8 : 0);
                int cc = 2 * ks + ((lane >> 3) & 1);
                uint32_t b0, b1, b2, b3;
                ldsm4(b0, b1, b2, b3, Bs + swz(rr, cc));
#pragma unroll
                for (int mt = 0; mt < 2; mt++) {
                    mma_f16(acc[mt][2 * nb],     ah[mt], b0, b1);
                    mma_f16(acc[mt][2 * nb + 1], ah[mt], b2, b3);
                }
            }
        }
        __syncthreads();
        stg = (stg + 1 == 3) ? 0 : stg + 1;
        nstg = (nstg + 1 == 3) ? 0 : nstg + 1;
    }

    const float qscale = (MODE == 0) ? __expf(*log_temp) * 1.4426950408889634f : 1.f;
#pragma unroll
    for (int mt = 0; mt < 2; mt++) {
#pragma unroll
        for (int i = 0; i < 2; i++) {
            const int gm = m0 + 32 * wm + 16 * mt + (lane >> 2) + i * 8;
#pragma unroll
            for (int nt = 0; nt < 8; nt++) {
                const int gn = n0 + 64 * wn + 8 * nt + 2 * (lane & 3);
                float v0 = acc[mt][nt][2 * i], v1 = acc[mt][nt][2 * i + 1];
                if (MODE == 0) {
                    const int seg = gn >> 9, nn = gn & 511;
                    const int h = nn >> 6, d = nn & 63;
                    const int bI = gm >> 11, s = gm & 2047;
                    size_t idx = ((size_t)((bI * 8 + h) * 2048 + s)) * 64 + d;
                    if (seg == 0) { v0 *= qscale; v1 *= qscale; }
                    __half* dst = (seg == 0) ? q : (seg == 1) ? k : v;
                    *reinterpret_cast<uint32_t*>(dst + idx) = pkh(v0, v1);
                } else {
                    float2 bb = *reinterpret_cast<const float2*>(bias + gn);
                    float2 o = make_float2(v0 + bb.x, v1 + bb.y);
                    *reinterpret_cast<float2*>(outp + (size_t)gm * 512 + gn) = o;
                }
            }
        }
    }
}

// ---------------- attention v3: 4-stage KV ring, single barrier per tile -----
__global__ void __launch_bounds__(256, 1)
attn_mma(const __half* __restrict__ qg, const __half* __restrict__ kg,
         const __half* __restrict__ vg, __half* __restrict__ aout) {
    extern __shared__ char smc[];
    const uint32_t sb = smem_u32(smc);
    const int tid = threadIdx.x, w = tid >> 5, lane = tid & 31;
    const int q0 = blockIdx.x * 256;
    const int bh = blockIdx.y, b = bh >> 3, h = bh & 7;
    const uint32_t KO = 0, VO = 16384, STG = 32768, QO = 131072;  // 4 stages then Q

    const size_t bho = (size_t)bh * 2048 * 64;

    // Q tile (256 x 64) -> smem
#pragma unroll
    for (int i = tid; i < 2048; i += 256) {
        int r = i >> 3, c = i & 7;
        *reinterpret_cast<uint4*>(smc + QO + swz(r, c)) =
            *reinterpret_cast<const uint4*>(qg + bho + (size_t)(q0 + r) * 64 + c * 8);
    }

    auto issue = [&](int t, int stg) {
        const size_t o = bho + (size_t)t * 128 * 64;
        uint32_t base = sb + (uint32_t)stg * STG;
#pragma unroll
        for (int i = tid; i < 1024; i += 256) {
            int r = i >> 3, c = i & 7;
            uint32_t off = swz(r, c);
            size_t g = o + (size_t)r * 64 + c * 8;
            cp16(base + KO + off, kg + g);
            cp16(base + VO + off, vg + g);
        }
    };
    issue(0, 0); CP_COMMIT();
    issue(1, 1); CP_COMMIT();
    __syncthreads();   // Q visible

    // Q fragments for both m16 tiles (persist)
    uint32_t aq[2][4][4];
#pragma unroll
    for (int mt = 0; mt < 2; mt++) {
        int rr = 32 * w + 16 * mt + (lane & 7) + ((lane >> 3) & 1) * 8;
#pragma unroll
        for (int ks = 0; ks < 4; ks++) {
            int cc = 2 * ks + (lane >> 4);
            ldsm4(aq[mt][ks][0], aq[mt][ks][1], aq[mt][ks][2], aq[mt][ks][3],
                  sb + QO + swz(rr, cc));
        }
    }

    float O[2][8][4] = {};
    float l[2][2] = {};
    const int rbase = q0 + 32 * w + (lane >> 2);

    for (int t = 0; t < 16; t++) {
        if (t + 2 < 16) issue(t + 2, (t + 2) & 3);
        CP_COMMIT();
        CP_WAIT2();
        __syncthreads();   // tile t loads complete (all threads)

        const uint32_t stgb = sb + (uint32_t)(t & 3) * STG;
        const uint32_t Ks = stgb + KO, Vs = stgb + VO;

#pragma unroll
        for (int half = 0; half < 2; half++) {
            float S[2][8][4] = {};
#pragma unroll
            for (int ks = 0; ks < 4; ks++) {
#pragma unroll
                for (int ntp = 0; ntp < 4; ntp++) {
                    uint32_t b0, b1, b2, b3;
                    int rr = 16 * (4 * half + ntp) + (lane & 7) + ((lane >> 4) ? 8 : 0);
                    int cc = 2 * ks + ((lane >> 3) & 1);
                    ldsm4(b0, b1, b2, b3, Ks + swz(rr, cc));
#pragma unroll
                    for (int mt = 0; mt < 2; mt++) {
                        mma_f16(S[mt][2 * ntp],     aq[mt][ks], b0, b1);
                        mma_f16(S[mt][2 * ntp + 1], aq[mt][ks], b2, b3);
                    }
                }
            }

            uint32_t ep[2][8][2];
#pragma unroll
            for (int mt = 0; mt < 2; mt++) {
                const int qi0 = rbase + 16 * mt, qi1 = qi0 + 8;
#pragma unroll
                for (int s = 0; s < 8; s++) {
                    int jc = t * 128 + 64 * half + 8 * s + 2 * (lane & 3);
                    float e0 = (jc     == qi0) ? 0.f : exp2f(S[mt][s][0]);
                    float e1 = (jc + 1 == qi0) ? 0.f : exp2f(S[mt][s][1]);
                    float e2 = (jc     == qi1) ? 0.f : exp2f(S[mt][s][2]);
                    float e3 = (jc + 1 == qi1) ? 0.f : exp2f(S[mt][s][3]);
                    l[mt][0] += e0 + e1;
                    l[mt][1] += e2 + e3;
                    ep[mt][s][0] = pkh(e0, e1);
                    ep[mt][s][1] = pkh(e2, e3);
                }
            }

#pragma unroll
            for (int ks2 = 0; ks2 < 4; ks2++) {
#pragma unroll
                for (int ntp = 0; ntp < 4; ntp++) {
                    uint32_t b0, b1, b2, b3;
                    int rr = 16 * (4 * half + ks2) + (lane & 7) + ((lane >> 3) & 1) * 8;
                    int cc = 2 * ntp + (lane >> 4);
                    ldsm4t(b0, b1, b2, b3, Vs + swz(rr, cc));
#pragma unroll
                    for (int mt = 0; mt < 2; mt++) {
                        uint32_t ap[4] = { ep[mt][2 * ks2][0], ep[mt][2 * ks2][1],
                                           ep[mt][2 * ks2 + 1][0], ep[mt][2 * ks2 + 1][1] };
                        mma_f16(O[mt][2 * ntp],     ap, b0, b1);
                        mma_f16(O[mt][2 * ntp + 1], ap, b2, b3);
                    }
                }
            }
        }
        // no end-of-loop barrier: 4-stage ring guarantees no overwrite hazard
    }

#pragma unroll
    for (int mt = 0; mt < 2; mt++) {
#pragma unroll
        for (int i = 0; i < 2; i++) {
            float li = l[mt][i];
            li += __shfl_xor_sync(0xffffffffu, li, 1);
            li += __shfl_xor_sync(0xffffffffu, li, 2);
            const float inv = 1.f / li;
            const size_t gm = (size_t)(b * 2048 + rbase + 16 * mt + 8 * i);
#pragma unroll
            for (int nt = 0; nt < 8; nt++) {
                const int d = 8 * nt + 2 * (lane & 3);
                size_t idx = gm * INNER + h * DHEAD + d;
                *reinterpret_cast<uint32_t*>(aout + idx) =
                    pkh(O[mt][nt][2 * i] * inv, O[mt][nt][2 * i + 1] * inv);
            }
        }
    }
}

// ---------------- launch -----------------------------------------------------
extern "C" void kernel_launch(void* const* d_in, const int* in_sizes, int n_in,
                              void* d_out, int out_size) {
    const float* x        = (const float*)d_in[0];
    const float* W_qkv    = (const float*)d_in[1];
    const float* log_temp = (const float*)d_in[2];
    const float* W_out    = (const float*)d_in[3];
    const float* b_out    = (const float*)d_in[4];
    float* out = (float*)d_out;

    __half *xh, *wq, *wo, *q, *k, *v, *a;
    cudaGetSymbolAddress((void**)&xh, g_x);
    cudaGetSymbolAddress((void**)&wq, g_wq);
    cudaGetSymbolAddress((void**)&wo, g_wo);
    cudaGetSymbolAddress((void**)&q, g_q);
    cudaGetSymbolAddress((void**)&k, g_k);
    cudaGetSymbolAddress((void**)&v, g_v);
    cudaGetSymbolAddress((void**)&a, g_a);

    const int GSM = 98304;    // 3 stages x 32KB
    const int ASM = 163840;   // 4 KV stages x 32KB + Q 32KB
    cudaFuncSetAttribute(gemm_mma<0>, cudaFuncAttributeMaxDynamicSharedMemorySize, GSM);
    cudaFuncSetAttribute(gemm_mma<1>, cudaFuncAttributeMaxDynamicSharedMemorySize, GSM);
    cudaFuncSetAttribute(attn_mma,    cudaFuncAttributeMaxDynamicSharedMemorySize, ASM);

    k_convert<<<5120, 256>>>(x, W_qkv, W_out, xh, wq, wo);

    // 1) QKV projection (q pre-scaled by exp(log_temp)*log2e)
    gemm_mma<0><<<dim3(12, 64), 256, GSM>>>(xh, wq, DIMX, q, k, v,
                                            log_temp, nullptr, nullptr);
    // 2) attention (q-tile 256, 4-stage ring, 1 barrier/tile)
    attn_mma<<<dim3(SSEQ / 256, BB * HEADS), 256, ASM>>>(q, k, v, a);
    // 3) output projection + bias -> fp32
    gemm_mma<1><<<dim3(4, 64), 256, GSM>>>(a, wo, INNER, nullptr, nullptr, nullptr,
                                           nullptr, b_out, out);
}